// round 10
// baseline (speedup 1.0000x reference)
#include <cuda_runtime.h>
#include <math.h>

// ---- problem dims ----
#define BN 128
#define CC 512
#define HW 196
#define KF 2
#define AA 2000
#define TT 20
#define EE 300
#define LH 1024
#define MH 512
#define G4 4096   // 4*LH
#define KSL 4     // K slices for zgemm
#define KS  (LH / KSL)  // 256

// ---- scratch (device globals; no runtime allocation) ----
__device__ float g_maps[BN * HW];
__device__ float g_denom[BN];
__device__ float g_hmeas[BN * MH];
__device__ float g_att[BN * CC];
__device__ float g_root[BN * AA];               // logits -> softmax probs (in place)
__device__ float g_X[(size_t)BN * TT * G4];     // emb@Wx + b_lstm, precomputed
__device__ float g_zp[KSL][BN * G4];            // per-K-slice gate partials
__device__ float g_h[2][BN * LH];               // double-buffered hidden state
__device__ float g_c[BN * LH];
__device__ float g_hlast[BN * LH];
__device__ float g_enc[BN * AA];

// ---- Find: maps[b,hw] = relu(w0.f) * relu(w1.f); denom[b] = sum + 1e-6 ----
__global__ void find_kernel(const float* __restrict__ feat,
                            const int* __restrict__ find_inst,
                            const float* __restrict__ W_find) {
    int b = blockIdx.x;
    __shared__ float w0[CC], w1[CC];
    __shared__ float red[256];
    int i0 = find_inst[b * KF + 0], i1 = find_inst[b * KF + 1];
    for (int c = threadIdx.x; c < CC; c += blockDim.x) {
        w0[c] = W_find[(size_t)i0 * CC + c];
        w1[c] = W_find[(size_t)i1 * CC + c];
    }
    __syncthreads();
    float m = 0.f;
    int t = threadIdx.x;
    if (t < HW) {
        const float* fb = feat + (size_t)b * CC * HW + t;
        float a0 = 0.f, a1 = 0.f;
#pragma unroll 4
        for (int c = 0; c < CC; c++) {
            float f = fb[(size_t)c * HW];
            a0 = fmaf(w0[c], f, a0);
            a1 = fmaf(w1[c], f, a1);
        }
        a0 = fmaxf(a0, 0.f); a1 = fmaxf(a1, 0.f);
        m = a0 * a1;
        g_maps[b * HW + t] = m;
    }
    red[threadIdx.x] = m; __syncthreads();
    for (int s = 128; s > 0; s >>= 1) {
        if (threadIdx.x < s) red[threadIdx.x] += red[threadIdx.x + s];
        __syncthreads();
    }
    if (threadIdx.x == 0) g_denom[b] = red[0] + 1e-6f;
}

// ---- Describe attend: attended[b,c] = sum_hw (maps/denom)[hw] * feat[b,c,hw] ----
__global__ void attend_kernel(const float* __restrict__ feat) {
    int b = blockIdx.x;
    __shared__ float ms[HW];
    float inv = 1.f / g_denom[b];
    for (int t = threadIdx.x; t < HW; t += blockDim.x) ms[t] = g_maps[b * HW + t] * inv;
    __syncthreads();
    int c = threadIdx.x;  // blockDim = 512
    const float4* fb = (const float4*)(feat + (size_t)(b * CC + c) * HW);
    float acc = 0.f;
    for (int q = 0; q < HW / 4; q++) {
        float4 f = fb[q];
        acc = fmaf(ms[4 * q + 0], f.x, acc);
        acc = fmaf(ms[4 * q + 1], f.y, acc);
        acc = fmaf(ms[4 * q + 2], f.z, acc);
        acc = fmaf(ms[4 * q + 3], f.w, acc);
    }
    g_att[b * CC + c] = acc;
}

// ---- Measure hidden: h = relu(mflat @ W_meas1[r] + b_meas1[r]) (yes samples only) ----
__global__ void measure_kernel(const int* __restrict__ root,
                               const int* __restrict__ yes,
                               const float* __restrict__ W1,
                               const float* __restrict__ b1) {
    int b = blockIdx.y;
    if (yes[b] == 0) return;  // block-uniform
    __shared__ float mf[HW];
    for (int t = threadIdx.x; t < HW; t += blockDim.x) mf[t] = g_maps[b * HW + t];
    __syncthreads();
    int m = blockIdx.x * 256 + threadIdx.x;  // blockDim = 256
    int r = root[b];
    const float* W = W1 + (size_t)r * HW * MH + m;
    float acc = b1[r * MH + m];
#pragma unroll 4
    for (int i = 0; i < HW; i++) acc = fmaf(mf[i], W[(size_t)i * MH], acc);
    g_hmeas[b * MH + m] = fmaxf(acc, 0.f);
}

// ---- Root logits: yes -> h@W_meas2+b2 ; no -> attended@W_desc[r]+b_desc[r] ----
__global__ void rootlogits_kernel(const int* __restrict__ root,
                                  const int* __restrict__ yes,
                                  const float* __restrict__ Wm2,
                                  const float* __restrict__ bm2,
                                  const float* __restrict__ Wd,
                                  const float* __restrict__ bd) {
    int b = blockIdx.y;
    int a = blockIdx.x * blockDim.x + threadIdx.x;
    __shared__ float v[512];  // MH == CC == 512
    bool y = yes[b] != 0;
    int r = root[b];
    const float* src = y ? &g_hmeas[b * MH] : &g_att[b * CC];
    for (int i = threadIdx.x; i < 512; i += blockDim.x) v[i] = src[i];
    __syncthreads();
    if (a >= AA) return;
    const float* W = y ? (Wm2 + a) : (Wd + (size_t)r * CC * AA + a);
    float acc = y ? bm2[a] : bd[r * AA + a];
#pragma unroll 4
    for (int i = 0; i < 512; i++) acc = fmaf(v[i], W[(size_t)i * AA], acc);
    g_root[b * AA + a] = acc;
}

// ---- softmax over root logits (in place) ----
__global__ void softmax_root_kernel() {
    int b = blockIdx.x;
    __shared__ float red[256];
    int tid = threadIdx.x;
    float mx = -3.4e38f;
    for (int a = tid; a < AA; a += blockDim.x) mx = fmaxf(mx, g_root[b * AA + a]);
    red[tid] = mx; __syncthreads();
    for (int s = 128; s > 0; s >>= 1) { if (tid < s) red[tid] = fmaxf(red[tid], red[tid + s]); __syncthreads(); }
    mx = red[0]; __syncthreads();
    float sum = 0.f;
    for (int a = tid; a < AA; a += blockDim.x) {
        float e = expf(g_root[b * AA + a] - mx);
        g_root[b * AA + a] = e;
        sum += e;
    }
    red[tid] = sum; __syncthreads();
    for (int s = 128; s > 0; s >>= 1) { if (tid < s) red[tid] += red[tid + s]; __syncthreads(); }
    float inv = 1.f / red[0];
    for (int a = tid; a < AA; a += blockDim.x) g_root[b * AA + a] *= inv;
}

// ---- X = emb@Wx + b_lstm for all (b,t) rows: 2560 x 4096, K=300 ----
__global__ __launch_bounds__(128) void xw_kernel(const int* __restrict__ question,
                                                 const float* __restrict__ Eemb,
                                                 const float* __restrict__ Wx,
                                                 const float* __restrict__ b_lstm) {
    const int RT = 16;
    int tid = threadIdx.x;
    int n0 = blockIdx.x * 256 + tid * 2;      // grid.x = G4/256 = 16
    int r0 = blockIdx.y * RT;                 // grid.y = 160
    __shared__ __align__(16) float es[RT][EE];
    __shared__ int toks[RT];
    if (tid < RT) toks[tid] = question[r0 + tid];
    __syncthreads();
    for (int idx = tid; idx < RT * EE; idx += 128) {
        int rr = idx / EE, e = idx - rr * EE;
        es[rr][e] = Eemb[(size_t)toks[rr] * EE + e];
    }
    __syncthreads();
    float2 bias = *(const float2*)&b_lstm[n0];
    float accx[RT], accy[RT];
#pragma unroll
    for (int rr = 0; rr < RT; rr++) { accx[rr] = bias.x; accy[rr] = bias.y; }
    for (int e = 0; e < EE; e += 4) {   // EE = 300 = 4*75
        float2 w0 = *(const float2*)&Wx[(size_t)e * G4 + n0];
        float2 w1 = *(const float2*)&Wx[(size_t)(e + 1) * G4 + n0];
        float2 w2 = *(const float2*)&Wx[(size_t)(e + 2) * G4 + n0];
        float2 w3 = *(const float2*)&Wx[(size_t)(e + 3) * G4 + n0];
#pragma unroll
        for (int rr = 0; rr < RT; rr++) {
            float4 ev = *(const float4*)&es[rr][e];
            accx[rr] = fmaf(ev.x, w0.x, accx[rr]);
            accy[rr] = fmaf(ev.x, w0.y, accy[rr]);
            accx[rr] = fmaf(ev.y, w1.x, accx[rr]);
            accy[rr] = fmaf(ev.y, w1.y, accy[rr]);
            accx[rr] = fmaf(ev.z, w2.x, accx[rr]);
            accy[rr] = fmaf(ev.z, w2.y, accy[rr]);
            accx[rr] = fmaf(ev.w, w3.x, accx[rr]);
            accy[rr] = fmaf(ev.w, w3.y, accy[rr]);
        }
    }
#pragma unroll
    for (int rr = 0; rr < RT; rr++) {
        float2 o; o.x = accx[rr]; o.y = accy[rr];
        *(float2*)&g_X[(size_t)(r0 + rr) * G4 + n0] = o;
    }
}

// ---- zgemm v3: partial z over one K slice. grid (16,16,4), 128 thr.
//      2 output cols/thread (float2 weights), BT=8 rows, 4k chunk prefetch.
//      slice 0 seeds with X (bias + emb term); others start at 0. ----
__global__ __launch_bounds__(128, 8) void zgemm_kernel(const float* __restrict__ Wh,
                                                       int t, int hsel) {
    const int BT = 8;
    __shared__ __align__(16) float hs[BT * KS];  // 8 KB
    int tid = threadIdx.x;
    int n0 = blockIdx.x * 256 + tid * 2;         // grid.x = 16
    int b0 = blockIdx.y * BT;                    // grid.y = 16
    int ks = blockIdx.z * KS;                    // grid.z = 4

    for (int i = tid; i < BT * KS / 4; i += 128) {
        int bb = i >> 6;                          // KS/4 = 64
        int q  = i & 63;
        *(float4*)&hs[bb * KS + q * 4] =
            *(const float4*)&g_h[hsel][(size_t)(b0 + bb) * LH + ks + q * 4];
    }

    const float* Wp = Wh + (size_t)ks * G4 + n0;
    float2 wcur[4], wnxt[4];
#pragma unroll
    for (int kk = 0; kk < 4; kk++) wcur[kk] = *(const float2*)&Wp[(size_t)kk * G4];

    float2 acc[BT];
    if (blockIdx.z == 0) {
#pragma unroll
        for (int bb = 0; bb < BT; bb++)
            acc[bb] = *(const float2*)&g_X[((size_t)(b0 + bb) * TT + t) * G4 + n0];
    } else {
#pragma unroll
        for (int bb = 0; bb < BT; bb++) { acc[bb].x = 0.f; acc[bb].y = 0.f; }
    }
    __syncthreads();

    for (int k = 0; k < KS; k += 4) {
        if (k + 4 < KS) {
#pragma unroll
            for (int kk = 0; kk < 4; kk++)
                wnxt[kk] = *(const float2*)&Wp[(size_t)(k + 4 + kk) * G4];
        }
#pragma unroll
        for (int bb = 0; bb < BT; bb++) {
            float4 hv = *(const float4*)&hs[bb * KS + k];  // warp-broadcast
            acc[bb].x = fmaf(hv.x, wcur[0].x, acc[bb].x);
            acc[bb].y = fmaf(hv.x, wcur[0].y, acc[bb].y);
            acc[bb].x = fmaf(hv.y, wcur[1].x, acc[bb].x);
            acc[bb].y = fmaf(hv.y, wcur[1].y, acc[bb].y);
            acc[bb].x = fmaf(hv.z, wcur[2].x, acc[bb].x);
            acc[bb].y = fmaf(hv.z, wcur[2].y, acc[bb].y);
            acc[bb].x = fmaf(hv.w, wcur[3].x, acc[bb].x);
            acc[bb].y = fmaf(hv.w, wcur[3].y, acc[bb].y);
        }
#pragma unroll
        for (int kk = 0; kk < 4; kk++) wcur[kk] = wnxt[kk];
    }
#pragma unroll
    for (int bb = 0; bb < BT; bb++)
        *(float2*)&g_zp[blockIdx.z][(size_t)(b0 + bb) * G4 + n0] = acc[bb];
}

// ---- LSTM gate at t=0: h0 = 0, so z0 = X[:,0,:]; no GEMM needed ----
__global__ void gate0_kernel(const int* __restrict__ length) {
    int b = blockIdx.x;
    bool last = (length[b] == 1);
    const float* xb = &g_X[(size_t)b * TT * G4];
    for (int j = threadIdx.x; j < LH; j += blockDim.x) {
        float zi = xb[j];
        float zg = xb[j + 2 * LH];
        float zo = xb[j + 3 * LH];
        float ig = 1.f / (1.f + expf(-zi));
        float og = 1.f / (1.f + expf(-zo));
        float c = ig * tanhf(zg);           // cprev = 0
        float h = og * tanhf(c);
        g_c[b * LH + j] = c;
        g_h[1][b * LH + j] = h;
        if (last) g_hlast[b * LH + j] = h;
    }
}

// ---- LSTM gates: sum 4 K-slice partials (fixed order), update c/h ----
__global__ void gate_kernel(const int* __restrict__ length, int t, int hnext) {
    int b = blockIdx.x;
    int j = threadIdx.x * 4;   // 256 threads -> 1024 j, 4 per thread
    bool last = (length[b] - 1) == t;
    float4 z[4];
#pragma unroll
    for (int g = 0; g < 4; g++) {
        size_t idx = (size_t)b * G4 + g * LH + j;
        float4 s0 = *(const float4*)&g_zp[0][idx];
        float4 s1 = *(const float4*)&g_zp[1][idx];
        float4 s2 = *(const float4*)&g_zp[2][idx];
        float4 s3 = *(const float4*)&g_zp[3][idx];
        z[g].x = s0.x + s1.x + s2.x + s3.x;
        z[g].y = s0.y + s1.y + s2.y + s3.y;
        z[g].z = s0.z + s1.z + s2.z + s3.z;
        z[g].w = s0.w + s1.w + s2.w + s3.w;
    }
    float4 cprev = *(const float4*)&g_c[b * LH + j];
    float4 cout, hout;
    {
        float zi[4] = {z[0].x, z[0].y, z[0].z, z[0].w};
        float zf[4] = {z[1].x, z[1].y, z[1].z, z[1].w};
        float zg[4] = {z[2].x, z[2].y, z[2].z, z[2].w};
        float zo[4] = {z[3].x, z[3].y, z[3].z, z[3].w};
        float cp[4] = {cprev.x, cprev.y, cprev.z, cprev.w};
        float co[4], ho[4];
#pragma unroll
        for (int l = 0; l < 4; l++) {
            float ig = 1.f / (1.f + expf(-zi[l]));
            float fg = 1.f / (1.f + expf(-zf[l]));
            float og = 1.f / (1.f + expf(-zo[l]));
            float c = fg * cp[l] + ig * tanhf(zg[l]);
            co[l] = c;
            ho[l] = og * tanhf(c);
        }
        cout.x = co[0]; cout.y = co[1]; cout.z = co[2]; cout.w = co[3];
        hout.x = ho[0]; hout.y = ho[1]; hout.z = ho[2]; hout.w = ho[3];
    }
    *(float4*)&g_c[b * LH + j] = cout;
    *(float4*)&g_h[hnext][b * LH + j] = hout;
    if (last) *(float4*)&g_hlast[b * LH + j] = hout;
}

// ---- enc logits = h_last @ W_enc + b_enc : 128 x 2000, K=1024 ----
__global__ __launch_bounds__(128) void enc_kernel(const float* __restrict__ Wenc,
                                                  const float* __restrict__ benc) {
    const int BT = 8;
    __shared__ __align__(16) float hs[BT * LH];  // 32 KB
    int n = blockIdx.x * 128 + threadIdx.x;      // grid.x = 16
    int b0 = blockIdx.y * BT;                    // grid.y = 16
    {
        const float4* src = (const float4*)&g_hlast[b0 * LH];
        float4* dst = (float4*)hs;
        for (int i = threadIdx.x; i < BT * LH / 4; i += 128) dst[i] = src[i];
    }
    __syncthreads();
    if (n >= AA) return;
    float acc[BT];
    float bias = benc[n];
#pragma unroll
    for (int bb = 0; bb < BT; bb++) acc[bb] = bias;
    for (int k = 0; k < LH; k += 4) {
        float w0 = Wenc[(size_t)k * AA + n];
        float w1 = Wenc[(size_t)(k + 1) * AA + n];
        float w2 = Wenc[(size_t)(k + 2) * AA + n];
        float w3 = Wenc[(size_t)(k + 3) * AA + n];
#pragma unroll
        for (int bb = 0; bb < BT; bb++) {
            float4 hv = *(const float4*)&hs[bb * LH + k];
            acc[bb] = fmaf(hv.x, w0, acc[bb]);
            acc[bb] = fmaf(hv.y, w1, acc[bb]);
            acc[bb] = fmaf(hv.z, w2, acc[bb]);
            acc[bb] = fmaf(hv.w, w3, acc[bb]);
        }
    }
#pragma unroll
    for (int bb = 0; bb < BT; bb++) g_enc[(b0 + bb) * AA + n] = acc[bb];
}

// ---- final: softmax(enc) and out = sqrt(root_pred * enc_pred) ----
__global__ void final_kernel(float* __restrict__ out) {
    int b = blockIdx.x;
    __shared__ float red[256];
    int tid = threadIdx.x;
    float mx = -3.4e38f;
    for (int a = tid; a < AA; a += blockDim.x) mx = fmaxf(mx, g_enc[b * AA + a]);
    red[tid] = mx; __syncthreads();
    for (int s = 128; s > 0; s >>= 1) { if (tid < s) red[tid] = fmaxf(red[tid], red[tid + s]); __syncthreads(); }
    mx = red[0]; __syncthreads();
    float sum = 0.f;
    for (int a = tid; a < AA; a += blockDim.x) sum += expf(g_enc[b * AA + a] - mx);
    red[tid] = sum; __syncthreads();
    for (int s = 128; s > 0; s >>= 1) { if (tid < s) red[tid] += red[tid + s]; __syncthreads(); }
    float inv = 1.f / red[0];
    for (int a = tid; a < AA; a += blockDim.x) {
        float e = expf(g_enc[b * AA + a] - mx) * inv;
        out[b * AA + a] = sqrtf(g_root[b * AA + a] * e);
    }
}

extern "C" void kernel_launch(void* const* d_in, const int* in_sizes, int n_in,
                              void* d_out, int out_size) {
    const float* features        = (const float*)d_in[0];
    const int* question          = (const int*)d_in[1];
    const int* length            = (const int*)d_in[2];
    const int* yesno             = (const int*)d_in[3];   // bool upcast; nonzero test
    const int* root_inst         = (const int*)d_in[4];
    const int* find_inst         = (const int*)d_in[5];
    const float* W_find          = (const float*)d_in[6];
    const float* W_meas1         = (const float*)d_in[7];
    const float* b_meas1         = (const float*)d_in[8];
    const float* W_meas2         = (const float*)d_in[9];
    const float* b_meas2         = (const float*)d_in[10];
    const float* W_desc          = (const float*)d_in[11];
    const float* b_desc          = (const float*)d_in[12];
    const float* E_emb           = (const float*)d_in[13];
    const float* Wx              = (const float*)d_in[14];
    const float* Wh              = (const float*)d_in[15];
    const float* b_lstm          = (const float*)d_in[16];
    const float* W_enc           = (const float*)d_in[17];
    const float* b_enc           = (const float*)d_in[18];
    float* out = (float*)d_out;

    // Side stream + fork/join events for overlapping the module network with
    // the encoder path. Created once (resources only; the launched work is
    // identical on every call, so determinism and graph capture are preserved).
    static cudaStream_t s_mod = nullptr;
    static cudaEvent_t ev_fork = nullptr, ev_join = nullptr;
    if (s_mod == nullptr) {
        cudaStreamCreateWithFlags(&s_mod, cudaStreamNonBlocking);
        cudaEventCreateWithFlags(&ev_fork, cudaEventDisableTiming);
        cudaEventCreateWithFlags(&ev_join, cudaEventDisableTiming);
    }

    // fork: module network on s_mod
    cudaEventRecord(ev_fork, 0);
    cudaStreamWaitEvent(s_mod, ev_fork, 0);
    find_kernel<<<BN, 256, 0, s_mod>>>(features, find_inst, W_find);
    attend_kernel<<<BN, 512, 0, s_mod>>>(features);
    measure_kernel<<<dim3(2, BN), 256, 0, s_mod>>>(root_inst, yesno, W_meas1, b_meas1);
    rootlogits_kernel<<<dim3(8, BN), 256, 0, s_mod>>>(root_inst, yesno, W_meas2, b_meas2, W_desc, b_desc);
    softmax_root_kernel<<<BN, 256, 0, s_mod>>>();
    cudaEventRecord(ev_join, s_mod);

    // main stream: question encoder
    xw_kernel<<<dim3(G4 / 256, (BN * TT) / 16), 128>>>(question, E_emb, Wx, b_lstm);
    gate0_kernel<<<BN, 256>>>(length);                       // t = 0: z = X, h0 = 0
    for (int t = 1; t < TT; t++) {
        zgemm_kernel<<<dim3(G4 / 256, BN / 8, KSL), 128>>>(Wh, t, t & 1);
        gate_kernel<<<BN, 256>>>(length, t, (t + 1) & 1);
    }
    enc_kernel<<<dim3((AA + 127) / 128, BN / 8), 128>>>(W_enc, b_enc);

    // join: final blend needs g_root from the module-network stream
    cudaStreamWaitEvent(0, ev_join, 0);
    final_kernel<<<BN, 256>>>(out);
}

// round 14
// speedup vs baseline: 1.0574x; 1.0574x over previous
#include <cuda_runtime.h>
#include <cuda_bf16.h>
#include <stdint.h>
#include <math.h>

// ---- problem dims ----
#define BN 128
#define CC 512
#define HW 196
#define KF 2
#define AA 2000
#define TT 20
#define EE 300
#define LH 1024
#define MH 512
#define G4 4096   // 4*LH
#define KB 3072   // split-bf16 GEMM K (= 3*LH)
#define KC 64     // K chunk
#define NCH (KB / KC)  // 48

// ---- scratch (device globals; no runtime allocation) ----
__device__ float g_maps[BN * HW];
__device__ float g_denom[BN];
__device__ float g_hmeas[BN * MH];
__device__ float g_att[BN * CC];
__device__ float g_root[BN * AA];
__device__ float g_X[(size_t)BN * TT * G4];     // emb@Wx + b_lstm
__device__ float g_z[BN * G4];                  // gate pre-activations
__device__ __nv_bfloat16 g_hA[BN][2048];        // [m][k]: Hh (0..1023) | Hl (1024..2047)
__device__ __nv_bfloat16 g_BT[G4][KB];          // [n][k]: Wh_h | Wh_h | Wh_l (transposed)
__device__ float g_c[BN * LH];
__device__ float g_hlast[BN * LH];
__device__ float g_enc[BN * AA];

// ---- prep: transpose + split Wh into g_BT (bf16 hi/hi/lo), once per launch ----
__global__ void prep_kernel(const float* __restrict__ Wh) {
    __shared__ float tile[32][33];
    int kt = blockIdx.y * 32;   // grid.y = LH/32 = 32
    int nt = blockIdx.x * 32;   // grid.x = G4/32 = 128
    int tx = threadIdx.x & 31, ty = threadIdx.x >> 5;  // 256 threads
    for (int r = ty; r < 32; r += 8)
        tile[r][tx] = Wh[(size_t)(kt + r) * G4 + nt + tx];
    __syncthreads();
    for (int r = ty; r < 32; r += 8) {
        int n = nt + r;
        float v = tile[tx][r];           // Wh[kt+tx][n]
        __nv_bfloat16 hi = __float2bfloat16(v);
        __nv_bfloat16 lo = __float2bfloat16(v - __bfloat162float(hi));
        g_BT[n][kt + tx]        = hi;
        g_BT[n][1024 + kt + tx] = hi;
        g_BT[n][2048 + kt + tx] = lo;
    }
}

// ---- Find ----
__global__ void find_kernel(const float* __restrict__ feat,
                            const int* __restrict__ find_inst,
                            const float* __restrict__ W_find) {
    int b = blockIdx.x;
    __shared__ float w0[CC], w1[CC];
    __shared__ float red[256];
    int i0 = find_inst[b * KF + 0], i1 = find_inst[b * KF + 1];
    for (int c = threadIdx.x; c < CC; c += blockDim.x) {
        w0[c] = W_find[(size_t)i0 * CC + c];
        w1[c] = W_find[(size_t)i1 * CC + c];
    }
    __syncthreads();
    float m = 0.f;
    int t = threadIdx.x;
    if (t < HW) {
        const float* fb = feat + (size_t)b * CC * HW + t;
        float a0 = 0.f, a1 = 0.f;
#pragma unroll 4
        for (int c = 0; c < CC; c++) {
            float f = fb[(size_t)c * HW];
            a0 = fmaf(w0[c], f, a0);
            a1 = fmaf(w1[c], f, a1);
        }
        a0 = fmaxf(a0, 0.f); a1 = fmaxf(a1, 0.f);
        m = a0 * a1;
        g_maps[b * HW + t] = m;
    }
    red[threadIdx.x] = m; __syncthreads();
    for (int s = 128; s > 0; s >>= 1) {
        if (threadIdx.x < s) red[threadIdx.x] += red[threadIdx.x + s];
        __syncthreads();
    }
    if (threadIdx.x == 0) g_denom[b] = red[0] + 1e-6f;
}

// ---- Describe attend ----
__global__ void attend_kernel(const float* __restrict__ feat) {
    int b = blockIdx.x;
    __shared__ float ms[HW];
    float inv = 1.f / g_denom[b];
    for (int t = threadIdx.x; t < HW; t += blockDim.x) ms[t] = g_maps[b * HW + t] * inv;
    __syncthreads();
    int c = threadIdx.x;  // blockDim = 512
    const float4* fb = (const float4*)(feat + (size_t)(b * CC + c) * HW);
    float acc = 0.f;
    for (int q = 0; q < HW / 4; q++) {
        float4 f = fb[q];
        acc = fmaf(ms[4 * q + 0], f.x, acc);
        acc = fmaf(ms[4 * q + 1], f.y, acc);
        acc = fmaf(ms[4 * q + 2], f.z, acc);
        acc = fmaf(ms[4 * q + 3], f.w, acc);
    }
    g_att[b * CC + c] = acc;
}

// ---- Measure hidden ----
__global__ void measure_kernel(const int* __restrict__ root,
                               const int* __restrict__ yes,
                               const float* __restrict__ W1,
                               const float* __restrict__ b1) {
    int b = blockIdx.y;
    if (yes[b] == 0) return;
    __shared__ float mf[HW];
    for (int t = threadIdx.x; t < HW; t += blockDim.x) mf[t] = g_maps[b * HW + t];
    __syncthreads();
    int m = blockIdx.x * 256 + threadIdx.x;
    int r = root[b];
    const float* W = W1 + (size_t)r * HW * MH + m;
    float acc = b1[r * MH + m];
#pragma unroll 4
    for (int i = 0; i < HW; i++) acc = fmaf(mf[i], W[(size_t)i * MH], acc);
    g_hmeas[b * MH + m] = fmaxf(acc, 0.f);
}

// ---- Root logits ----
__global__ void rootlogits_kernel(const int* __restrict__ root,
                                  const int* __restrict__ yes,
                                  const float* __restrict__ Wm2,
                                  const float* __restrict__ bm2,
                                  const float* __restrict__ Wd,
                                  const float* __restrict__ bd) {
    int b = blockIdx.y;
    int a = blockIdx.x * blockDim.x + threadIdx.x;
    __shared__ float v[512];
    bool y = yes[b] != 0;
    int r = root[b];
    const float* src = y ? &g_hmeas[b * MH] : &g_att[b * CC];
    for (int i = threadIdx.x; i < 512; i += blockDim.x) v[i] = src[i];
    __syncthreads();
    if (a >= AA) return;
    const float* W = y ? (Wm2 + a) : (Wd + (size_t)r * CC * AA + a);
    float acc = y ? bm2[a] : bd[r * AA + a];
#pragma unroll 4
    for (int i = 0; i < 512; i++) acc = fmaf(v[i], W[(size_t)i * AA], acc);
    g_root[b * AA + a] = acc;
}

// ---- softmax over root logits ----
__global__ void softmax_root_kernel() {
    int b = blockIdx.x;
    __shared__ float red[256];
    int tid = threadIdx.x;
    float mx = -3.4e38f;
    for (int a = tid; a < AA; a += blockDim.x) mx = fmaxf(mx, g_root[b * AA + a]);
    red[tid] = mx; __syncthreads();
    for (int s = 128; s > 0; s >>= 1) { if (tid < s) red[tid] = fmaxf(red[tid], red[tid + s]); __syncthreads(); }
    mx = red[0]; __syncthreads();
    float sum = 0.f;
    for (int a = tid; a < AA; a += blockDim.x) {
        float e = expf(g_root[b * AA + a] - mx);
        g_root[b * AA + a] = e;
        sum += e;
    }
    red[tid] = sum; __syncthreads();
    for (int s = 128; s > 0; s >>= 1) { if (tid < s) red[tid] += red[tid + s]; __syncthreads(); }
    float inv = 1.f / red[0];
    for (int a = tid; a < AA; a += blockDim.x) g_root[b * AA + a] *= inv;
}

// ---- X = emb@Wx + b_lstm : 2560 x 4096, K=300 ----
__global__ __launch_bounds__(128) void xw_kernel(const int* __restrict__ question,
                                                 const float* __restrict__ Eemb,
                                                 const float* __restrict__ Wx,
                                                 const float* __restrict__ b_lstm) {
    const int RT = 16;
    int tid = threadIdx.x;
    int n0 = blockIdx.x * 256 + tid * 2;
    int r0 = blockIdx.y * RT;
    __shared__ __align__(16) float es[RT][EE];
    __shared__ int toks[RT];
    if (tid < RT) toks[tid] = question[r0 + tid];
    __syncthreads();
    for (int idx = tid; idx < RT * EE; idx += 128) {
        int rr = idx / EE, e = idx - rr * EE;
        es[rr][e] = Eemb[(size_t)toks[rr] * EE + e];
    }
    __syncthreads();
    float2 bias = *(const float2*)&b_lstm[n0];
    float accx[RT], accy[RT];
#pragma unroll
    for (int rr = 0; rr < RT; rr++) { accx[rr] = bias.x; accy[rr] = bias.y; }
    for (int e = 0; e < EE; e += 4) {
        float2 w0 = *(const float2*)&Wx[(size_t)e * G4 + n0];
        float2 w1 = *(const float2*)&Wx[(size_t)(e + 1) * G4 + n0];
        float2 w2 = *(const float2*)&Wx[(size_t)(e + 2) * G4 + n0];
        float2 w3 = *(const float2*)&Wx[(size_t)(e + 3) * G4 + n0];
#pragma unroll
        for (int rr = 0; rr < RT; rr++) {
            float4 ev = *(const float4*)&es[rr][e];
            accx[rr] = fmaf(ev.x, w0.x, accx[rr]);
            accy[rr] = fmaf(ev.x, w0.y, accy[rr]);
            accx[rr] = fmaf(ev.y, w1.x, accx[rr]);
            accy[rr] = fmaf(ev.y, w1.y, accy[rr]);
            accx[rr] = fmaf(ev.z, w2.x, accx[rr]);
            accy[rr] = fmaf(ev.z, w2.y, accy[rr]);
            accx[rr] = fmaf(ev.w, w3.x, accx[rr]);
            accy[rr] = fmaf(ev.w, w3.y, accy[rr]);
        }
    }
#pragma unroll
    for (int rr = 0; rr < RT; rr++) {
        float2 o; o.x = accx[rr]; o.y = accy[rr];
        *(float2*)&g_X[(size_t)(r0 + rr) * G4 + n0] = o;
    }
}

// ---- zgemm_tc: Z = X + [Hh|Hl|Hh] @ g_BT^T via mma.sync bf16, fp32 accum.
//      grid (64 n-blocks, 2 m-blocks), 128 threads (4 warps, 2x2 warp grid).
//      Tile 64x64, KC=64 double-buffered smem (pitch 72 -> conflict-free frags). ----
__global__ __launch_bounds__(128) void zgemm_tc(int t) {
    __shared__ __align__(16) __nv_bfloat16 As[2][64][72];
    __shared__ __align__(16) __nv_bfloat16 Bs[2][64][72];
    const int tid = threadIdx.x;
    const int warp = tid >> 5, lane = tid & 31;
    const int gq = lane >> 2, tq = lane & 3;
    const int n0 = blockIdx.x * 64, m0 = blockIdx.y * 64;
    const int wm = (warp & 1) * 32, wn = (warp >> 1) * 32;
    const int arow = tid >> 3, aseg = tid & 7;   // staging: rows arow+16i, 16B seg

    // seed accumulators from X (c-fragment layout of m16n8)
    float acc[2][4][4];
#pragma unroll
    for (int mi = 0; mi < 2; mi++)
#pragma unroll
        for (int ni = 0; ni < 4; ni++) {
            int row0 = m0 + wm + mi * 16 + gq;
            int col = n0 + wn + ni * 8 + 2 * tq;
            float2 v0 = *(const float2*)&g_X[((size_t)row0 * TT + t) * G4 + col];
            float2 v1 = *(const float2*)&g_X[((size_t)(row0 + 8) * TT + t) * G4 + col];
            acc[mi][ni][0] = v0.x; acc[mi][ni][1] = v0.y;
            acc[mi][ni][2] = v1.x; acc[mi][ni][3] = v1.y;
        }

    uint4 ra[4], rb[4];
    // prologue: stage chunk 0
#pragma unroll
    for (int i = 0; i < 4; i++) {
        ra[i] = *(const uint4*)&g_hA[m0 + arow + 16 * i][aseg * 8];
        rb[i] = *(const uint4*)&g_BT[n0 + arow + 16 * i][aseg * 8];
    }
#pragma unroll
    for (int i = 0; i < 4; i++) {
        *(uint4*)&As[0][arow + 16 * i][aseg * 8] = ra[i];
        *(uint4*)&Bs[0][arow + 16 * i][aseg * 8] = rb[i];
    }
    __syncthreads();

    for (int c = 0; c < NCH; c++) {
        int buf = c & 1;
        if (c + 1 < NCH) {
            int k0 = (c + 1) * KC;
            int ka = (k0 >= 2048) ? (k0 - 2048) : k0;   // A col-mapping: third block re-reads Hh
#pragma unroll
            for (int i = 0; i < 4; i++) {
                ra[i] = *(const uint4*)&g_hA[m0 + arow + 16 * i][ka + aseg * 8];
                rb[i] = *(const uint4*)&g_BT[n0 + arow + 16 * i][k0 + aseg * 8];
            }
        }
#pragma unroll
        for (int ks = 0; ks < KC; ks += 16) {
            uint32_t a[2][4], b[4][2];
#pragma unroll
            for (int mi = 0; mi < 2; mi++) {
                a[mi][0] = *(const uint32_t*)&As[buf][wm + mi * 16 + gq    ][ks + 2 * tq];
                a[mi][1] = *(const uint32_t*)&As[buf][wm + mi * 16 + gq + 8][ks + 2 * tq];
                a[mi][2] = *(const uint32_t*)&As[buf][wm + mi * 16 + gq    ][ks + 2 * tq + 8];
                a[mi][3] = *(const uint32_t*)&As[buf][wm + mi * 16 + gq + 8][ks + 2 * tq + 8];
            }
#pragma unroll
            for (int ni = 0; ni < 4; ni++) {
                b[ni][0] = *(const uint32_t*)&Bs[buf][wn + ni * 8 + gq][ks + 2 * tq];
                b[ni][1] = *(const uint32_t*)&Bs[buf][wn + ni * 8 + gq][ks + 2 * tq + 8];
            }
#pragma unroll
            for (int mi = 0; mi < 2; mi++)
#pragma unroll
                for (int ni = 0; ni < 4; ni++)
                    asm volatile(
                        "mma.sync.aligned.m16n8k16.row.col.f32.bf16.bf16.f32 "
                        "{%0,%1,%2,%3}, {%4,%5,%6,%7}, {%8,%9}, {%0,%1,%2,%3};"
                        : "+f"(acc[mi][ni][0]), "+f"(acc[mi][ni][1]),
                          "+f"(acc[mi][ni][2]), "+f"(acc[mi][ni][3])
                        : "r"(a[mi][0]), "r"(a[mi][1]), "r"(a[mi][2]), "r"(a[mi][3]),
                          "r"(b[ni][0]), "r"(b[ni][1]));
        }
        if (c + 1 < NCH) {
#pragma unroll
            for (int i = 0; i < 4; i++) {
                *(uint4*)&As[buf ^ 1][arow + 16 * i][aseg * 8] = ra[i];
                *(uint4*)&Bs[buf ^ 1][arow + 16 * i][aseg * 8] = rb[i];
            }
            __syncthreads();
        }
    }

    // epilogue: z store
#pragma unroll
    for (int mi = 0; mi < 2; mi++)
#pragma unroll
        for (int ni = 0; ni < 4; ni++) {
            int row0 = m0 + wm + mi * 16 + gq;
            int col = n0 + wn + ni * 8 + 2 * tq;
            *(float2*)&g_z[(size_t)row0 * G4 + col] = make_float2(acc[mi][ni][0], acc[mi][ni][1]);
            *(float2*)&g_z[(size_t)(row0 + 8) * G4 + col] = make_float2(acc[mi][ni][2], acc[mi][ni][3]);
        }
}

// ---- gate helpers: write c, h (bf16 hi/lo into g_hA), hlast ----
__device__ __forceinline__ void gate_store(int b, int j, const float* zi, const float* zf,
                                           const float* zg, const float* zo,
                                           const float* cp, bool use_cp, bool last) {
    float co[4], ho[4];
#pragma unroll
    for (int l = 0; l < 4; l++) {
        float ig = 1.f / (1.f + expf(-zi[l]));
        float og = 1.f / (1.f + expf(-zo[l]));
        float c = ig * tanhf(zg[l]);
        if (use_cp) {
            float fg = 1.f / (1.f + expf(-zf[l]));
            c += fg * cp[l];
        }
        co[l] = c;
        ho[l] = og * tanhf(c);
    }
    *(float4*)&g_c[b * LH + j] = make_float4(co[0], co[1], co[2], co[3]);
    __nv_bfloat16 hi[4], lo[4];
#pragma unroll
    for (int l = 0; l < 4; l++) {
        hi[l] = __float2bfloat16(ho[l]);
        lo[l] = __float2bfloat16(ho[l] - __bfloat162float(hi[l]));
    }
    __nv_bfloat162* ph = (__nv_bfloat162*)&g_hA[b][j];
    ph[0] = __halves2bfloat162(hi[0], hi[1]);
    ph[1] = __halves2bfloat162(hi[2], hi[3]);
    __nv_bfloat162* pl = (__nv_bfloat162*)&g_hA[b][1024 + j];
    pl[0] = __halves2bfloat162(lo[0], lo[1]);
    pl[1] = __halves2bfloat162(lo[2], lo[3]);
    if (last) *(float4*)&g_hlast[b * LH + j] = make_float4(ho[0], ho[1], ho[2], ho[3]);
}

// ---- t=0: z0 = X[:,0,:], c0 = 0 ----
__global__ void gate0_kernel(const int* __restrict__ length) {
    int b = blockIdx.x;
    int j = threadIdx.x * 4;   // 256 threads
    bool last = (length[b] == 1);
    const float* xb = &g_X[(size_t)b * TT * G4];
    float4 zi4 = *(const float4*)&xb[j];
    float4 zg4 = *(const float4*)&xb[j + 2 * LH];
    float4 zo4 = *(const float4*)&xb[j + 3 * LH];
    float zi[4] = {zi4.x, zi4.y, zi4.z, zi4.w};
    float zg[4] = {zg4.x, zg4.y, zg4.z, zg4.w};
    float zo[4] = {zo4.x, zo4.y, zo4.z, zo4.w};
    float dummy[4] = {0, 0, 0, 0};
    gate_store(b, j, zi, dummy, zg, zo, dummy, false, last);
}

// ---- t>=1: gates from g_z ----
__global__ void gate_kernel(const int* __restrict__ length, int t) {
    int b = blockIdx.x;
    int j = threadIdx.x * 4;   // 256 threads
    bool last = (length[b] - 1) == t;
    const float* zb = &g_z[(size_t)b * G4];
    float4 zi4 = *(const float4*)&zb[j];
    float4 zf4 = *(const float4*)&zb[j + LH];
    float4 zg4 = *(const float4*)&zb[j + 2 * LH];
    float4 zo4 = *(const float4*)&zb[j + 3 * LH];
    float4 cp4 = *(const float4*)&g_c[b * LH + j];
    float zi[4] = {zi4.x, zi4.y, zi4.z, zi4.w};
    float zf[4] = {zf4.x, zf4.y, zf4.z, zf4.w};
    float zg[4] = {zg4.x, zg4.y, zg4.z, zg4.w};
    float zo[4] = {zo4.x, zo4.y, zo4.z, zo4.w};
    float cp[4] = {cp4.x, cp4.y, cp4.z, cp4.w};
    gate_store(b, j, zi, zf, zg, zo, cp, true, last);
}

// ---- enc logits = h_last @ W_enc + b_enc ----
__global__ __launch_bounds__(128) void enc_kernel(const float* __restrict__ Wenc,
                                                  const float* __restrict__ benc) {
    const int BT = 8;
    __shared__ __align__(16) float hs[BT * LH];
    int n = blockIdx.x * 128 + threadIdx.x;
    int b0 = blockIdx.y * BT;
    {
        const float4* src = (const float4*)&g_hlast[b0 * LH];
        float4* dst = (float4*)hs;
        for (int i = threadIdx.x; i < BT * LH / 4; i += 128) dst[i] = src[i];
    }
    __syncthreads();
    if (n >= AA) return;
    float acc[BT];
    float bias = benc[n];
#pragma unroll
    for (int bb = 0; bb < BT; bb++) acc[bb] = bias;
    for (int k = 0; k < LH; k += 4) {
        float w0 = Wenc[(size_t)k * AA + n];
        float w1 = Wenc[(size_t)(k + 1) * AA + n];
        float w2 = Wenc[(size_t)(k + 2) * AA + n];
        float w3 = Wenc[(size_t)(k + 3) * AA + n];
#pragma unroll
        for (int bb = 0; bb < BT; bb++) {
            float4 hv = *(const float4*)&hs[bb * LH + k];
            acc[bb] = fmaf(hv.x, w0, acc[bb]);
            acc[bb] = fmaf(hv.y, w1, acc[bb]);
            acc[bb] = fmaf(hv.z, w2, acc[bb]);
            acc[bb] = fmaf(hv.w, w3, acc[bb]);
        }
    }
#pragma unroll
    for (int bb = 0; bb < BT; bb++) g_enc[(b0 + bb) * AA + n] = acc[bb];
}

// ---- final ----
__global__ void final_kernel(float* __restrict__ out) {
    int b = blockIdx.x;
    __shared__ float red[256];
    int tid = threadIdx.x;
    float mx = -3.4e38f;
    for (int a = tid; a < AA; a += blockDim.x) mx = fmaxf(mx, g_enc[b * AA + a]);
    red[tid] = mx; __syncthreads();
    for (int s = 128; s > 0; s >>= 1) { if (tid < s) red[tid] = fmaxf(red[tid], red[tid + s]); __syncthreads(); }
    mx = red[0]; __syncthreads();
    float sum = 0.f;
    for (int a = tid; a < AA; a += blockDim.x) sum += expf(g_enc[b * AA + a] - mx);
    red[tid] = sum; __syncthreads();
    for (int s = 128; s > 0; s >>= 1) { if (tid < s) red[tid] += red[tid + s]; __syncthreads(); }
    float inv = 1.f / red[0];
    for (int a = tid; a < AA; a += blockDim.x) {
        float e = expf(g_enc[b * AA + a] - mx) * inv;
        out[b * AA + a] = sqrtf(g_root[b * AA + a] * e);
    }
}

extern "C" void kernel_launch(void* const* d_in, const int* in_sizes, int n_in,
                              void* d_out, int out_size) {
    const float* features        = (const float*)d_in[0];
    const int* question          = (const int*)d_in[1];
    const int* length            = (const int*)d_in[2];
    const int* yesno             = (const int*)d_in[3];
    const int* root_inst         = (const int*)d_in[4];
    const int* find_inst         = (const int*)d_in[5];
    const float* W_find          = (const float*)d_in[6];
    const float* W_meas1         = (const float*)d_in[7];
    const float* b_meas1         = (const float*)d_in[8];
    const float* W_meas2         = (const float*)d_in[9];
    const float* b_meas2         = (const float*)d_in[10];
    const float* W_desc          = (const float*)d_in[11];
    const float* b_desc          = (const float*)d_in[12];
    const float* E_emb           = (const float*)d_in[13];
    const float* Wx              = (const float*)d_in[14];
    const float* Wh              = (const float*)d_in[15];
    const float* b_lstm          = (const float*)d_in[16];
    const float* W_enc           = (const float*)d_in[17];
    const float* b_enc           = (const float*)d_in[18];
    float* out = (float*)d_out;

    static cudaStream_t s_mod = nullptr;
    static cudaEvent_t ev_fork = nullptr, ev_prep = nullptr, ev_join = nullptr;
    if (s_mod == nullptr) {
        cudaStreamCreateWithFlags(&s_mod, cudaStreamNonBlocking);
        cudaEventCreateWithFlags(&ev_fork, cudaEventDisableTiming);
        cudaEventCreateWithFlags(&ev_prep, cudaEventDisableTiming);
        cudaEventCreateWithFlags(&ev_join, cudaEventDisableTiming);
    }

    // fork: Wh prep + module network on side stream
    cudaEventRecord(ev_fork, 0);
    cudaStreamWaitEvent(s_mod, ev_fork, 0);
    prep_kernel<<<dim3(G4 / 32, LH / 32), 256, 0, s_mod>>>(Wh);
    cudaEventRecord(ev_prep, s_mod);
    find_kernel<<<BN, 256, 0, s_mod>>>(features, find_inst, W_find);
    attend_kernel<<<BN, 512, 0, s_mod>>>(features);
    measure_kernel<<<dim3(2, BN), 256, 0, s_mod>>>(root_inst, yesno, W_meas1, b_meas1);
    rootlogits_kernel<<<dim3(8, BN), 256, 0, s_mod>>>(root_inst, yesno, W_meas2, b_meas2, W_desc, b_desc);
    softmax_root_kernel<<<BN, 256, 0, s_mod>>>();
    cudaEventRecord(ev_join, s_mod);

    // main: question encoder
    xw_kernel<<<dim3(G4 / 256, (BN * TT) / 16), 128>>>(question, E_emb, Wx, b_lstm);
    gate0_kernel<<<BN, 256>>>(length);
    cudaStreamWaitEvent(0, ev_prep, 0);   // g_BT ready before first tensor GEMM
    for (int t = 1; t < TT; t++) {
        zgemm_tc<<<dim3(G4 / 64, BN / 64), 128>>>(t);
        gate_kernel<<<BN, 256>>>(length, t);
    }
    enc_kernel<<<dim3((AA + 127) / 128, BN / 8), 128>>>(W_enc, b_enc);

    // join
    cudaStreamWaitEvent(0, ev_join, 0);
    final_kernel<<<BN, 256>>>(out);
}

// round 15
// speedup vs baseline: 1.3064x; 1.2355x over previous
#include <cuda_runtime.h>
#include <cuda_bf16.h>
#include <stdint.h>
#include <math.h>

// ---- problem dims ----
#define BN 128
#define CC 512
#define HW 196
#define KF 2
#define AA 2000
#define TT 20
#define EE 300
#define LH 1024
#define MH 512
#define G4 4096   // 4*LH
#define KB 3072   // split-bf16 GEMM K (= 3*LH)
#define KC 64     // K chunk
#define NCHS 24   // chunks per K slice (KB/2/KC)

// ---- scratch (device globals; no runtime allocation) ----
__device__ float g_maps[BN * HW];
__device__ float g_denom[BN];
__device__ float g_hmeas[BN * MH];
__device__ float g_att[BN * CC];
__device__ float g_root[BN * AA];
__device__ float g_X[(size_t)BN * TT * G4];     // emb@Wx + b_lstm
__device__ float g_zp[2][BN * G4];              // per-K-slice gate partials
__device__ __nv_bfloat16 g_hA[BN][2048];        // [m][k]: Hh | Hl
__device__ __nv_bfloat16 g_BT[G4][KB];          // [n][k]: Wh_h | Wh_h | Wh_l
__device__ float g_c[BN * LH];
__device__ float g_hlast[BN * LH];
__device__ float g_enc[BN * AA];

__device__ __forceinline__ void cp16(void* smem, const void* gmem) {
    uint32_t s = (uint32_t)__cvta_generic_to_shared(smem);
    asm volatile("cp.async.ca.shared.global [%0], [%1], 16;" :: "r"(s), "l"(gmem));
}

// ---- prep: transpose + split Wh into g_BT (bf16 hi/hi/lo) ----
__global__ void prep_kernel(const float* __restrict__ Wh) {
    __shared__ float tile[32][33];
    int kt = blockIdx.y * 32;
    int nt = blockIdx.x * 32;
    int tx = threadIdx.x & 31, ty = threadIdx.x >> 5;
    for (int r = ty; r < 32; r += 8)
        tile[r][tx] = Wh[(size_t)(kt + r) * G4 + nt + tx];
    __syncthreads();
    for (int r = ty; r < 32; r += 8) {
        int n = nt + r;
        float v = tile[tx][r];
        __nv_bfloat16 hi = __float2bfloat16(v);
        __nv_bfloat16 lo = __float2bfloat16(v - __bfloat162float(hi));
        g_BT[n][kt + tx]        = hi;
        g_BT[n][1024 + kt + tx] = hi;
        g_BT[n][2048 + kt + tx] = lo;
    }
}

// ---- Find ----
__global__ void find_kernel(const float* __restrict__ feat,
                            const int* __restrict__ find_inst,
                            const float* __restrict__ W_find) {
    int b = blockIdx.x;
    __shared__ float w0[CC], w1[CC];
    __shared__ float red[256];
    int i0 = find_inst[b * KF + 0], i1 = find_inst[b * KF + 1];
    for (int c = threadIdx.x; c < CC; c += blockDim.x) {
        w0[c] = W_find[(size_t)i0 * CC + c];
        w1[c] = W_find[(size_t)i1 * CC + c];
    }
    __syncthreads();
    float m = 0.f;
    int t = threadIdx.x;
    if (t < HW) {
        const float* fb = feat + (size_t)b * CC * HW + t;
        float a0 = 0.f, a1 = 0.f;
#pragma unroll 4
        for (int c = 0; c < CC; c++) {
            float f = fb[(size_t)c * HW];
            a0 = fmaf(w0[c], f, a0);
            a1 = fmaf(w1[c], f, a1);
        }
        a0 = fmaxf(a0, 0.f); a1 = fmaxf(a1, 0.f);
        m = a0 * a1;
        g_maps[b * HW + t] = m;
    }
    red[threadIdx.x] = m; __syncthreads();
    for (int s = 128; s > 0; s >>= 1) {
        if (threadIdx.x < s) red[threadIdx.x] += red[threadIdx.x + s];
        __syncthreads();
    }
    if (threadIdx.x == 0) g_denom[b] = red[0] + 1e-6f;
}

// ---- Describe attend ----
__global__ void attend_kernel(const float* __restrict__ feat) {
    int b = blockIdx.x;
    __shared__ float ms[HW];
    float inv = 1.f / g_denom[b];
    for (int t = threadIdx.x; t < HW; t += blockDim.x) ms[t] = g_maps[b * HW + t] * inv;
    __syncthreads();
    int c = threadIdx.x;
    const float4* fb = (const float4*)(feat + (size_t)(b * CC + c) * HW);
    float acc = 0.f;
    for (int q = 0; q < HW / 4; q++) {
        float4 f = fb[q];
        acc = fmaf(ms[4 * q + 0], f.x, acc);
        acc = fmaf(ms[4 * q + 1], f.y, acc);
        acc = fmaf(ms[4 * q + 2], f.z, acc);
        acc = fmaf(ms[4 * q + 3], f.w, acc);
    }
    g_att[b * CC + c] = acc;
}

// ---- Measure hidden ----
__global__ void measure_kernel(const int* __restrict__ root,
                               const int* __restrict__ yes,
                               const float* __restrict__ W1,
                               const float* __restrict__ b1) {
    int b = blockIdx.y;
    if (yes[b] == 0) return;
    __shared__ float mf[HW];
    for (int t = threadIdx.x; t < HW; t += blockDim.x) mf[t] = g_maps[b * HW + t];
    __syncthreads();
    int m = blockIdx.x * 256 + threadIdx.x;
    int r = root[b];
    const float* W = W1 + (size_t)r * HW * MH + m;
    float acc = b1[r * MH + m];
#pragma unroll 4
    for (int i = 0; i < HW; i++) acc = fmaf(mf[i], W[(size_t)i * MH], acc);
    g_hmeas[b * MH + m] = fmaxf(acc, 0.f);
}

// ---- Root logits ----
__global__ void rootlogits_kernel(const int* __restrict__ root,
                                  const int* __restrict__ yes,
                                  const float* __restrict__ Wm2,
                                  const float* __restrict__ bm2,
                                  const float* __restrict__ Wd,
                                  const float* __restrict__ bd) {
    int b = blockIdx.y;
    int a = blockIdx.x * blockDim.x + threadIdx.x;
    __shared__ float v[512];
    bool y = yes[b] != 0;
    int r = root[b];
    const float* src = y ? &g_hmeas[b * MH] : &g_att[b * CC];
    for (int i = threadIdx.x; i < 512; i += blockDim.x) v[i] = src[i];
    __syncthreads();
    if (a >= AA) return;
    const float* W = y ? (Wm2 + a) : (Wd + (size_t)r * CC * AA + a);
    float acc = y ? bm2[a] : bd[r * AA + a];
#pragma unroll 4
    for (int i = 0; i < 512; i++) acc = fmaf(v[i], W[(size_t)i * AA], acc);
    g_root[b * AA + a] = acc;
}

// ---- softmax over root logits ----
__global__ void softmax_root_kernel() {
    int b = blockIdx.x;
    __shared__ float red[256];
    int tid = threadIdx.x;
    float mx = -3.4e38f;
    for (int a = tid; a < AA; a += blockDim.x) mx = fmaxf(mx, g_root[b * AA + a]);
    red[tid] = mx; __syncthreads();
    for (int s = 128; s > 0; s >>= 1) { if (tid < s) red[tid] = fmaxf(red[tid], red[tid + s]); __syncthreads(); }
    mx = red[0]; __syncthreads();
    float sum = 0.f;
    for (int a = tid; a < AA; a += blockDim.x) {
        float e = expf(g_root[b * AA + a] - mx);
        g_root[b * AA + a] = e;
        sum += e;
    }
    red[tid] = sum; __syncthreads();
    for (int s = 128; s > 0; s >>= 1) { if (tid < s) red[tid] += red[tid + s]; __syncthreads(); }
    float inv = 1.f / red[0];
    for (int a = tid; a < AA; a += blockDim.x) g_root[b * AA + a] *= inv;
}

// ---- X = emb@Wx + b_lstm : 2560 x 4096, K=300 ----
__global__ __launch_bounds__(128) void xw_kernel(const int* __restrict__ question,
                                                 const float* __restrict__ Eemb,
                                                 const float* __restrict__ Wx,
                                                 const float* __restrict__ b_lstm) {
    const int RT = 16;
    int tid = threadIdx.x;
    int n0 = blockIdx.x * 256 + tid * 2;
    int r0 = blockIdx.y * RT;
    __shared__ __align__(16) float es[RT][EE];
    __shared__ int toks[RT];
    if (tid < RT) toks[tid] = question[r0 + tid];
    __syncthreads();
    for (int idx = tid; idx < RT * EE; idx += 128) {
        int rr = idx / EE, e = idx - rr * EE;
        es[rr][e] = Eemb[(size_t)toks[rr] * EE + e];
    }
    __syncthreads();
    float2 bias = *(const float2*)&b_lstm[n0];
    float accx[RT], accy[RT];
#pragma unroll
    for (int rr = 0; rr < RT; rr++) { accx[rr] = bias.x; accy[rr] = bias.y; }
    for (int e = 0; e < EE; e += 4) {
        float2 w0 = *(const float2*)&Wx[(size_t)e * G4 + n0];
        float2 w1 = *(const float2*)&Wx[(size_t)(e + 1) * G4 + n0];
        float2 w2 = *(const float2*)&Wx[(size_t)(e + 2) * G4 + n0];
        float2 w3 = *(const float2*)&Wx[(size_t)(e + 3) * G4 + n0];
#pragma unroll
        for (int rr = 0; rr < RT; rr++) {
            float4 ev = *(const float4*)&es[rr][e];
            accx[rr] = fmaf(ev.x, w0.x, accx[rr]);
            accy[rr] = fmaf(ev.x, w0.y, accy[rr]);
            accx[rr] = fmaf(ev.y, w1.x, accx[rr]);
            accy[rr] = fmaf(ev.y, w1.y, accy[rr]);
            accx[rr] = fmaf(ev.z, w2.x, accx[rr]);
            accy[rr] = fmaf(ev.z, w2.y, accy[rr]);
            accx[rr] = fmaf(ev.w, w3.x, accx[rr]);
            accy[rr] = fmaf(ev.w, w3.y, accy[rr]);
        }
    }
#pragma unroll
    for (int rr = 0; rr < RT; rr++) {
        float2 o; o.x = accx[rr]; o.y = accy[rr];
        *(float2*)&g_X[(size_t)(r0 + rr) * G4 + n0] = o;
    }
}

// ---- zgemm_tc v2: K-split x2 + cp.async double-buffered staging.
//      grid (64 n, 2 m, 2 kslice), 128 threads, tile 64x64, KC=64. ----
__global__ __launch_bounds__(128) void zgemm_tc(int t) {
    __shared__ __align__(16) __nv_bfloat16 As[2][64][72];
    __shared__ __align__(16) __nv_bfloat16 Bs[2][64][72];
    const int tid = threadIdx.x;
    const int warp = tid >> 5, lane = tid & 31;
    const int gq = lane >> 2, tq = lane & 3;
    const int n0 = blockIdx.x * 64, m0 = blockIdx.y * 64;
    const int sl = blockIdx.z;
    const int kbase = sl * (KB / 2);
    const int wm = (warp & 1) * 32, wn = (warp >> 1) * 32;
    const int arow = tid >> 3, aseg = tid & 7;

    float acc[2][4][4];
    if (sl == 0) {
#pragma unroll
        for (int mi = 0; mi < 2; mi++)
#pragma unroll
            for (int ni = 0; ni < 4; ni++) {
                int row0 = m0 + wm + mi * 16 + gq;
                int col = n0 + wn + ni * 8 + 2 * tq;
                float2 v0 = *(const float2*)&g_X[((size_t)row0 * TT + t) * G4 + col];
                float2 v1 = *(const float2*)&g_X[((size_t)(row0 + 8) * TT + t) * G4 + col];
                acc[mi][ni][0] = v0.x; acc[mi][ni][1] = v0.y;
                acc[mi][ni][2] = v1.x; acc[mi][ni][3] = v1.y;
            }
    } else {
#pragma unroll
        for (int mi = 0; mi < 2; mi++)
#pragma unroll
            for (int ni = 0; ni < 4; ni++)
#pragma unroll
                for (int q = 0; q < 4; q++) acc[mi][ni][q] = 0.f;
    }

    auto stage = [&](int c, int buf) {
        int k0 = kbase + c * KC;
        int ka = (k0 >= 2048) ? (k0 - 2048) : k0;   // A: third K block re-reads Hh
#pragma unroll
        for (int i = 0; i < 4; i++) {
            cp16(&As[buf][arow + 16 * i][aseg * 8], &g_hA[m0 + arow + 16 * i][ka + aseg * 8]);
            cp16(&Bs[buf][arow + 16 * i][aseg * 8], &g_BT[n0 + arow + 16 * i][k0 + aseg * 8]);
        }
        asm volatile("cp.async.commit_group;");
    };

    stage(0, 0);
    for (int c = 0; c < NCHS; c++) {
        int buf = c & 1;
        if (c + 1 < NCHS) {
            stage(c + 1, buf ^ 1);
            asm volatile("cp.async.wait_group 1;");
        } else {
            asm volatile("cp.async.wait_group 0;");
        }
        __syncthreads();   // stage c landed, visible to all warps
#pragma unroll
        for (int ks = 0; ks < KC; ks += 16) {
            uint32_t a[2][4], b[4][2];
#pragma unroll
            for (int mi = 0; mi < 2; mi++) {
                a[mi][0] = *(const uint32_t*)&As[buf][wm + mi * 16 + gq    ][ks + 2 * tq];
                a[mi][1] = *(const uint32_t*)&As[buf][wm + mi * 16 + gq + 8][ks + 2 * tq];
                a[mi][2] = *(const uint32_t*)&As[buf][wm + mi * 16 + gq    ][ks + 2 * tq + 8];
                a[mi][3] = *(const uint32_t*)&As[buf][wm + mi * 16 + gq + 8][ks + 2 * tq + 8];
            }
#pragma unroll
            for (int ni = 0; ni < 4; ni++) {
                b[ni][0] = *(const uint32_t*)&Bs[buf][wn + ni * 8 + gq][ks + 2 * tq];
                b[ni][1] = *(const uint32_t*)&Bs[buf][wn + ni * 8 + gq][ks + 2 * tq + 8];
            }
#pragma unroll
            for (int mi = 0; mi < 2; mi++)
#pragma unroll
                for (int ni = 0; ni < 4; ni++)
                    asm volatile(
                        "mma.sync.aligned.m16n8k16.row.col.f32.bf16.bf16.f32 "
                        "{%0,%1,%2,%3}, {%4,%5,%6,%7}, {%8,%9}, {%0,%1,%2,%3};"
                        : "+f"(acc[mi][ni][0]), "+f"(acc[mi][ni][1]),
                          "+f"(acc[mi][ni][2]), "+f"(acc[mi][ni][3])
                        : "r"(a[mi][0]), "r"(a[mi][1]), "r"(a[mi][2]), "r"(a[mi][3]),
                          "r"(b[ni][0]), "r"(b[ni][1]));
        }
        __syncthreads();   // all warps done reading buf before stage(c+2) overwrites it
    }

#pragma unroll
    for (int mi = 0; mi < 2; mi++)
#pragma unroll
        for (int ni = 0; ni < 4; ni++) {
            int row0 = m0 + wm + mi * 16 + gq;
            int col = n0 + wn + ni * 8 + 2 * tq;
            *(float2*)&g_zp[sl][(size_t)row0 * G4 + col] = make_float2(acc[mi][ni][0], acc[mi][ni][1]);
            *(float2*)&g_zp[sl][(size_t)(row0 + 8) * G4 + col] = make_float2(acc[mi][ni][2], acc[mi][ni][3]);
        }
}

// ---- gate helpers: write c, h (bf16 hi/lo into g_hA), hlast ----
__device__ __forceinline__ void gate_store(int b, int j, const float* zi, const float* zf,
                                           const float* zg, const float* zo,
                                           const float* cp, bool use_cp, bool last) {
    float co[4], ho[4];
#pragma unroll
    for (int l = 0; l < 4; l++) {
        float ig = 1.f / (1.f + expf(-zi[l]));
        float og = 1.f / (1.f + expf(-zo[l]));
        float c = ig * tanhf(zg[l]);
        if (use_cp) {
            float fg = 1.f / (1.f + expf(-zf[l]));
            c += fg * cp[l];
        }
        co[l] = c;
        ho[l] = og * tanhf(c);
    }
    *(float4*)&g_c[b * LH + j] = make_float4(co[0], co[1], co[2], co[3]);
    __nv_bfloat16 hi[4], lo[4];
#pragma unroll
    for (int l = 0; l < 4; l++) {
        hi[l] = __float2bfloat16(ho[l]);
        lo[l] = __float2bfloat16(ho[l] - __bfloat162float(hi[l]));
    }
    __nv_bfloat162* ph = (__nv_bfloat162*)&g_hA[b][j];
    ph[0] = __halves2bfloat162(hi[0], hi[1]);
    ph[1] = __halves2bfloat162(hi[2], hi[3]);
    __nv_bfloat162* pl = (__nv_bfloat162*)&g_hA[b][1024 + j];
    pl[0] = __halves2bfloat162(lo[0], lo[1]);
    pl[1] = __halves2bfloat162(lo[2], lo[3]);
    if (last) *(float4*)&g_hlast[b * LH + j] = make_float4(ho[0], ho[1], ho[2], ho[3]);
}

// ---- t=0: z0 = X[:,0,:], c0 = 0 ----
__global__ void gate0_kernel(const int* __restrict__ length) {
    int b = blockIdx.x;
    int j = threadIdx.x * 4;
    bool last = (length[b] == 1);
    const float* xb = &g_X[(size_t)b * TT * G4];
    float4 zi4 = *(const float4*)&xb[j];
    float4 zg4 = *(const float4*)&xb[j + 2 * LH];
    float4 zo4 = *(const float4*)&xb[j + 3 * LH];
    float zi[4] = {zi4.x, zi4.y, zi4.z, zi4.w};
    float zg[4] = {zg4.x, zg4.y, zg4.z, zg4.w};
    float zo[4] = {zo4.x, zo4.y, zo4.z, zo4.w};
    float dummy[4] = {0, 0, 0, 0};
    gate_store(b, j, zi, dummy, zg, zo, dummy, false, last);
}

// ---- t>=1: gates from g_zp[0]+g_zp[1] ----
__global__ void gate_kernel(const int* __restrict__ length, int t) {
    int b = blockIdx.x;
    int j = threadIdx.x * 4;
    bool last = (length[b] - 1) == t;
    float4 z[4];
#pragma unroll
    for (int g = 0; g < 4; g++) {
        size_t idx = (size_t)b * G4 + g * LH + j;
        float4 s0 = *(const float4*)&g_zp[0][idx];
        float4 s1 = *(const float4*)&g_zp[1][idx];
        z[g].x = s0.x + s1.x; z[g].y = s0.y + s1.y;
        z[g].z = s0.z + s1.z; z[g].w = s0.w + s1.w;
    }
    float4 cp4 = *(const float4*)&g_c[b * LH + j];
    float zi[4] = {z[0].x, z[0].y, z[0].z, z[0].w};
    float zf[4] = {z[1].x, z[1].y, z[1].z, z[1].w};
    float zg[4] = {z[2].x, z[2].y, z[2].z, z[2].w};
    float zo[4] = {z[3].x, z[3].y, z[3].z, z[3].w};
    float cp[4] = {cp4.x, cp4.y, cp4.z, cp4.w};
    gate_store(b, j, zi, zf, zg, zo, cp, true, last);
}

// ---- enc logits = h_last @ W_enc + b_enc ----
__global__ __launch_bounds__(128) void enc_kernel(const float* __restrict__ Wenc,
                                                  const float* __restrict__ benc) {
    const int BT = 8;
    __shared__ __align__(16) float hs[BT * LH];
    int n = blockIdx.x * 128 + threadIdx.x;
    int b0 = blockIdx.y * BT;
    {
        const float4* src = (const float4*)&g_hlast[b0 * LH];
        float4* dst = (float4*)hs;
        for (int i = threadIdx.x; i < BT * LH / 4; i += 128) dst[i] = src[i];
    }
    __syncthreads();
    if (n >= AA) return;
    float acc[BT];
    float bias = benc[n];
#pragma unroll
    for (int bb = 0; bb < BT; bb++) acc[bb] = bias;
    for (int k = 0; k < LH; k += 4) {
        float w0 = Wenc[(size_t)k * AA + n];
        float w1 = Wenc[(size_t)(k + 1) * AA + n];
        float w2 = Wenc[(size_t)(k + 2) * AA + n];
        float w3 = Wenc[(size_t)(k + 3) * AA + n];
#pragma unroll
        for (int bb = 0; bb < BT; bb++) {
            float4 hv = *(const float4*)&hs[bb * LH + k];
            acc[bb] = fmaf(hv.x, w0, acc[bb]);
            acc[bb] = fmaf(hv.y, w1, acc[bb]);
            acc[bb] = fmaf(hv.z, w2, acc[bb]);
            acc[bb] = fmaf(hv.w, w3, acc[bb]);
        }
    }
#pragma unroll
    for (int bb = 0; bb < BT; bb++) g_enc[(b0 + bb) * AA + n] = acc[bb];
}

// ---- final ----
__global__ void final_kernel(float* __restrict__ out) {
    int b = blockIdx.x;
    __shared__ float red[256];
    int tid = threadIdx.x;
    float mx = -3.4e38f;
    for (int a = tid; a < AA; a += blockDim.x) mx = fmaxf(mx, g_enc[b * AA + a]);
    red[tid] = mx; __syncthreads();
    for (int s = 128; s > 0; s >>= 1) { if (tid < s) red[tid] = fmaxf(red[tid], red[tid + s]); __syncthreads(); }
    mx = red[0]; __syncthreads();
    float sum = 0.f;
    for (int a = tid; a < AA; a += blockDim.x) sum += expf(g_enc[b * AA + a] - mx);
    red[tid] = sum; __syncthreads();
    for (int s = 128; s > 0; s >>= 1) { if (tid < s) red[tid] += red[tid + s]; __syncthreads(); }
    float inv = 1.f / red[0];
    for (int a = tid; a < AA; a += blockDim.x) {
        float e = expf(g_enc[b * AA + a] - mx) * inv;
        out[b * AA + a] = sqrtf(g_root[b * AA + a] * e);
    }
}

extern "C" void kernel_launch(void* const* d_in, const int* in_sizes, int n_in,
                              void* d_out, int out_size) {
    const float* features        = (const float*)d_in[0];
    const int* question          = (const int*)d_in[1];
    const int* length            = (const int*)d_in[2];
    const int* yesno             = (const int*)d_in[3];
    const int* root_inst         = (const int*)d_in[4];
    const int* find_inst         = (const int*)d_in[5];
    const float* W_find          = (const float*)d_in[6];
    const float* W_meas1         = (const float*)d_in[7];
    const float* b_meas1         = (const float*)d_in[8];
    const float* W_meas2         = (const float*)d_in[9];
    const float* b_meas2         = (const float*)d_in[10];
    const float* W_desc          = (const float*)d_in[11];
    const float* b_desc          = (const float*)d_in[12];
    const float* E_emb           = (const float*)d_in[13];
    const float* Wx              = (const float*)d_in[14];
    const float* Wh              = (const float*)d_in[15];
    const float* b_lstm          = (const float*)d_in[16];
    const float* W_enc           = (const float*)d_in[17];
    const float* b_enc           = (const float*)d_in[18];
    float* out = (float*)d_out;

    static cudaStream_t s_mod = nullptr;
    static cudaEvent_t ev_fork = nullptr, ev_prep = nullptr, ev_join = nullptr;
    if (s_mod == nullptr) {
        cudaStreamCreateWithFlags(&s_mod, cudaStreamNonBlocking);
        cudaEventCreateWithFlags(&ev_fork, cudaEventDisableTiming);
        cudaEventCreateWithFlags(&ev_prep, cudaEventDisableTiming);
        cudaEventCreateWithFlags(&ev_join, cudaEventDisableTiming);
    }

    // fork: Wh prep + module network on side stream
    cudaEventRecord(ev_fork, 0);
    cudaStreamWaitEvent(s_mod, ev_fork, 0);
    prep_kernel<<<dim3(G4 / 32, LH / 32), 256, 0, s_mod>>>(Wh);
    cudaEventRecord(ev_prep, s_mod);
    find_kernel<<<BN, 256, 0, s_mod>>>(features, find_inst, W_find);
    attend_kernel<<<BN, 512, 0, s_mod>>>(features);
    measure_kernel<<<dim3(2, BN), 256, 0, s_mod>>>(root_inst, yesno, W_meas1, b_meas1);
    rootlogits_kernel<<<dim3(8, BN), 256, 0, s_mod>>>(root_inst, yesno, W_meas2, b_meas2, W_desc, b_desc);
    softmax_root_kernel<<<BN, 256, 0, s_mod>>>();
    cudaEventRecord(ev_join, s_mod);

    // main: question encoder
    xw_kernel<<<dim3(G4 / 256, (BN * TT) / 16), 128>>>(question, E_emb, Wx, b_lstm);
    gate0_kernel<<<BN, 256>>>(length);
    cudaStreamWaitEvent(0, ev_prep, 0);
    for (int t = 1; t < TT; t++) {
        zgemm_tc<<<dim3(G4 / 64, BN / 64, 2), 128>>>(t);
        gate_kernel<<<BN, 256>>>(length, t);
    }
    enc_kernel<<<dim3((AA + 127) / 128, BN / 8), 128>>>(W_enc, b_enc);

    // join
    cudaStreamWaitEvent(0, ev_join, 0);
    final_kernel<<<BN, 256>>>(out);
}

// round 16
// speedup vs baseline: 1.4595x; 1.1172x over previous
#include <cuda_runtime.h>
#include <cuda_bf16.h>
#include <stdint.h>
#include <math.h>

// ---- problem dims ----
#define BN 128
#define CC 512
#define HW 196
#define KF 2
#define AA 2000
#define TT 20
#define EE 300
#define LH 1024
#define MH 512
#define G4 4096   // 4*LH
#define KB 3072   // LSTM split-bf16 GEMM K (= 3*LH)
#define KC 64     // LSTM K chunk
#define NCHS 24   // chunks per K slice (KB/2/KC)
#define XKP 320   // padded emb K segment (300 -> 320)
#define XKB 960   // xw split K total (3*320)
#define XKC 32    // xw K chunk
#define XNCH (XKB / XKC)  // 30
#define MROWS (BN * TT)   // 2560

// ---- scratch (device globals; no runtime allocation) ----
__device__ float g_maps[BN * HW];
__device__ float g_denom[BN];
__device__ float g_hmeas[BN * MH];
__device__ float g_att[BN * CC];
__device__ float g_root[BN * AA];
__device__ float g_X[(size_t)BN * TT * G4];     // emb@Wx + b_lstm
__device__ float g_zp[2][BN * G4];              // per-K-slice gate partials
__device__ __nv_bfloat16 g_hA[BN][2048];        // [m][k]: Hh | Hl
__device__ __nv_bfloat16 g_BT[G4][KB];          // [n][k]: Wh_h | Wh_h | Wh_l
__device__ __nv_bfloat16 g_XA[MROWS][2 * XKP];  // [row][k]: Ehi(0..319) | Elo(320..639)
__device__ __nv_bfloat16 g_XBT[G4][XKB];        // [n][k]: Wx_h | Wx_h | Wx_l
__device__ float g_c[BN * LH];
__device__ float g_hlast[BN * LH];
__device__ float g_enc[BN * AA];

__device__ __forceinline__ void cp16(void* smem, const void* gmem) {
    uint32_t s = (uint32_t)__cvta_generic_to_shared(smem);
    asm volatile("cp.async.ca.shared.global [%0], [%1], 16;" :: "r"(s), "l"(gmem));
}

// ---- prep: transpose + split Wh into g_BT (bf16 hi/hi/lo) ----
__global__ void prep_kernel(const float* __restrict__ Wh) {
    __shared__ float tile[32][33];
    int kt = blockIdx.y * 32;
    int nt = blockIdx.x * 32;
    int tx = threadIdx.x & 31, ty = threadIdx.x >> 5;
    for (int r = ty; r < 32; r += 8)
        tile[r][tx] = Wh[(size_t)(kt + r) * G4 + nt + tx];
    __syncthreads();
    for (int r = ty; r < 32; r += 8) {
        int n = nt + r;
        float v = tile[tx][r];
        __nv_bfloat16 hi = __float2bfloat16(v);
        __nv_bfloat16 lo = __float2bfloat16(v - __bfloat162float(hi));
        g_BT[n][kt + tx]        = hi;
        g_BT[n][1024 + kt + tx] = hi;
        g_BT[n][2048 + kt + tx] = lo;
    }
}

// ---- prep xA: gather embeddings, split hi/lo, pad to 320 ----
__global__ void prep_xA(const int* __restrict__ question,
                        const float* __restrict__ Eemb) {
    int r = blockIdx.x;           // 0..2559
    int j = threadIdx.x;          // 0..319
    int tok = question[r];
    __nv_bfloat16 hi = __float2bfloat16(0.f), lo = hi;
    if (j < EE) {
        float v = Eemb[(size_t)tok * EE + j];
        hi = __float2bfloat16(v);
        lo = __float2bfloat16(v - __bfloat162float(hi));
    }
    g_XA[r][j] = hi;
    g_XA[r][XKP + j] = lo;
}

// ---- prep xB: transpose + split Wx into g_XBT (hi/hi/lo, padded) ----
__global__ void prep_xB(const float* __restrict__ Wx) {
    __shared__ float tile[32][33];
    int kt = blockIdx.y * 32;     // 0..288 (10 tiles, covers 320)
    int nt = blockIdx.x * 32;
    int tx = threadIdx.x & 31, ty = threadIdx.x >> 5;
    for (int r = ty; r < 32; r += 8) {
        int k = kt + r;
        tile[r][tx] = (k < EE) ? Wx[(size_t)k * G4 + nt + tx] : 0.f;
    }
    __syncthreads();
    for (int r = ty; r < 32; r += 8) {
        int n = nt + r;
        float v = tile[tx][r];
        __nv_bfloat16 hi = __float2bfloat16(v);
        __nv_bfloat16 lo = __float2bfloat16(v - __bfloat162float(hi));
        g_XBT[n][kt + tx]            = hi;
        g_XBT[n][XKP + kt + tx]      = hi;
        g_XBT[n][2 * XKP + kt + tx]  = lo;
    }
}

// ---- Find ----
__global__ void find_kernel(const float* __restrict__ feat,
                            const int* __restrict__ find_inst,
                            const float* __restrict__ W_find) {
    int b = blockIdx.x;
    __shared__ float w0[CC], w1[CC];
    __shared__ float red[256];
    int i0 = find_inst[b * KF + 0], i1 = find_inst[b * KF + 1];
    for (int c = threadIdx.x; c < CC; c += blockDim.x) {
        w0[c] = W_find[(size_t)i0 * CC + c];
        w1[c] = W_find[(size_t)i1 * CC + c];
    }
    __syncthreads();
    float m = 0.f;
    int t = threadIdx.x;
    if (t < HW) {
        const float* fb = feat + (size_t)b * CC * HW + t;
        float a0 = 0.f, a1 = 0.f;
#pragma unroll 4
        for (int c = 0; c < CC; c++) {
            float f = fb[(size_t)c * HW];
            a0 = fmaf(w0[c], f, a0);
            a1 = fmaf(w1[c], f, a1);
        }
        a0 = fmaxf(a0, 0.f); a1 = fmaxf(a1, 0.f);
        m = a0 * a1;
        g_maps[b * HW + t] = m;
    }
    red[threadIdx.x] = m; __syncthreads();
    for (int s = 128; s > 0; s >>= 1) {
        if (threadIdx.x < s) red[threadIdx.x] += red[threadIdx.x + s];
        __syncthreads();
    }
    if (threadIdx.x == 0) g_denom[b] = red[0] + 1e-6f;
}

// ---- Describe attend ----
__global__ void attend_kernel(const float* __restrict__ feat) {
    int b = blockIdx.x;
    __shared__ float ms[HW];
    float inv = 1.f / g_denom[b];
    for (int t = threadIdx.x; t < HW; t += blockDim.x) ms[t] = g_maps[b * HW + t] * inv;
    __syncthreads();
    int c = threadIdx.x;
    const float4* fb = (const float4*)(feat + (size_t)(b * CC + c) * HW);
    float acc = 0.f;
    for (int q = 0; q < HW / 4; q++) {
        float4 f = fb[q];
        acc = fmaf(ms[4 * q + 0], f.x, acc);
        acc = fmaf(ms[4 * q + 1], f.y, acc);
        acc = fmaf(ms[4 * q + 2], f.z, acc);
        acc = fmaf(ms[4 * q + 3], f.w, acc);
    }
    g_att[b * CC + c] = acc;
}

// ---- Measure hidden ----
__global__ void measure_kernel(const int* __restrict__ root,
                               const int* __restrict__ yes,
                               const float* __restrict__ W1,
                               const float* __restrict__ b1) {
    int b = blockIdx.y;
    if (yes[b] == 0) return;
    __shared__ float mf[HW];
    for (int t = threadIdx.x; t < HW; t += blockDim.x) mf[t] = g_maps[b * HW + t];
    __syncthreads();
    int m = blockIdx.x * 256 + threadIdx.x;
    int r = root[b];
    const float* W = W1 + (size_t)r * HW * MH + m;
    float acc = b1[r * MH + m];
#pragma unroll 4
    for (int i = 0; i < HW; i++) acc = fmaf(mf[i], W[(size_t)i * MH], acc);
    g_hmeas[b * MH + m] = fmaxf(acc, 0.f);
}

// ---- Root logits ----
__global__ void rootlogits_kernel(const int* __restrict__ root,
                                  const int* __restrict__ yes,
                                  const float* __restrict__ Wm2,
                                  const float* __restrict__ bm2,
                                  const float* __restrict__ Wd,
                                  const float* __restrict__ bd) {
    int b = blockIdx.y;
    int a = blockIdx.x * blockDim.x + threadIdx.x;
    __shared__ float v[512];
    bool y = yes[b] != 0;
    int r = root[b];
    const float* src = y ? &g_hmeas[b * MH] : &g_att[b * CC];
    for (int i = threadIdx.x; i < 512; i += blockDim.x) v[i] = src[i];
    __syncthreads();
    if (a >= AA) return;
    const float* W = y ? (Wm2 + a) : (Wd + (size_t)r * CC * AA + a);
    float acc = y ? bm2[a] : bd[r * AA + a];
#pragma unroll 4
    for (int i = 0; i < 512; i++) acc = fmaf(v[i], W[(size_t)i * AA], acc);
    g_root[b * AA + a] = acc;
}

// ---- softmax over root logits ----
__global__ void softmax_root_kernel() {
    int b = blockIdx.x;
    __shared__ float red[256];
    int tid = threadIdx.x;
    float mx = -3.4e38f;
    for (int a = tid; a < AA; a += blockDim.x) mx = fmaxf(mx, g_root[b * AA + a]);
    red[tid] = mx; __syncthreads();
    for (int s = 128; s > 0; s >>= 1) { if (tid < s) red[tid] = fmaxf(red[tid], red[tid + s]); __syncthreads(); }
    mx = red[0]; __syncthreads();
    float sum = 0.f;
    for (int a = tid; a < AA; a += blockDim.x) {
        float e = expf(g_root[b * AA + a] - mx);
        g_root[b * AA + a] = e;
        sum += e;
    }
    red[tid] = sum; __syncthreads();
    for (int s = 128; s > 0; s >>= 1) { if (tid < s) red[tid] += red[tid + s]; __syncthreads(); }
    float inv = 1.f / red[0];
    for (int a = tid; a < AA; a += blockDim.x) g_root[b * AA + a] *= inv;
}

// ---- xw_tc: X = [Ehi|Elo|Ehi] @ g_XBT^T + b_lstm via mma.sync bf16.
//      grid (32, 20), 256 thr (8 warps, 4m x 2n), tile 128x128, XKC=32. ----
__global__ __launch_bounds__(256) void xw_tc(const float* __restrict__ b_lstm) {
    __shared__ __align__(16) __nv_bfloat16 As[2][128][40];  // 20 KB
    __shared__ __align__(16) __nv_bfloat16 Bs[2][128][40];  // 20 KB
    const int tid = threadIdx.x;
    const int warp = tid >> 5, lane = tid & 31;
    const int gq = lane >> 2, tq = lane & 3;
    const int n0 = blockIdx.x * 128, m0 = blockIdx.y * 128;
    const int wm = (warp & 3) * 32, wn = (warp >> 2) * 64;
    const int arow = tid >> 2, aseg = tid & 3;   // rows 0..63 (+64), 4x16B segs

    float acc[2][8][4];
#pragma unroll
    for (int ni = 0; ni < 8; ni++) {
        int col = n0 + wn + ni * 8 + 2 * tq;
        float2 bv = *(const float2*)&b_lstm[col];
#pragma unroll
        for (int mi = 0; mi < 2; mi++) {
            acc[mi][ni][0] = bv.x; acc[mi][ni][1] = bv.y;
            acc[mi][ni][2] = bv.x; acc[mi][ni][3] = bv.y;
        }
    }

    auto stage = [&](int c, int buf) {
        int k0 = c * XKC;
        int ka = (k0 >= 2 * XKP) ? k0 - 2 * XKP : k0;  // A: [hi|lo|hi]
#pragma unroll
        for (int half = 0; half < 2; half++) {
            int r = arow + half * 64;
            cp16(&As[buf][r][aseg * 8], &g_XA[m0 + r][ka + aseg * 8]);
            cp16(&Bs[buf][r][aseg * 8], &g_XBT[n0 + r][k0 + aseg * 8]);
        }
        asm volatile("cp.async.commit_group;");
    };

    stage(0, 0);
    for (int c = 0; c < XNCH; c++) {
        int buf = c & 1;
        if (c + 1 < XNCH) {
            stage(c + 1, buf ^ 1);
            asm volatile("cp.async.wait_group 1;");
        } else {
            asm volatile("cp.async.wait_group 0;");
        }
        __syncthreads();
#pragma unroll
        for (int ks = 0; ks < XKC; ks += 16) {
            uint32_t a[2][4], b[8][2];
#pragma unroll
            for (int mi = 0; mi < 2; mi++) {
                a[mi][0] = *(const uint32_t*)&As[buf][wm + mi * 16 + gq    ][ks + 2 * tq];
                a[mi][1] = *(const uint32_t*)&As[buf][wm + mi * 16 + gq + 8][ks + 2 * tq];
                a[mi][2] = *(const uint32_t*)&As[buf][wm + mi * 16 + gq    ][ks + 2 * tq + 8];
                a[mi][3] = *(const uint32_t*)&As[buf][wm + mi * 16 + gq + 8][ks + 2 * tq + 8];
            }
#pragma unroll
            for (int ni = 0; ni < 8; ni++) {
                b[ni][0] = *(const uint32_t*)&Bs[buf][wn + ni * 8 + gq][ks + 2 * tq];
                b[ni][1] = *(const uint32_t*)&Bs[buf][wn + ni * 8 + gq][ks + 2 * tq + 8];
            }
#pragma unroll
            for (int mi = 0; mi < 2; mi++)
#pragma unroll
                for (int ni = 0; ni < 8; ni++)
                    asm volatile(
                        "mma.sync.aligned.m16n8k16.row.col.f32.bf16.bf16.f32 "
                        "{%0,%1,%2,%3}, {%4,%5,%6,%7}, {%8,%9}, {%0,%1,%2,%3};"
                        : "+f"(acc[mi][ni][0]), "+f"(acc[mi][ni][1]),
                          "+f"(acc[mi][ni][2]), "+f"(acc[mi][ni][3])
                        : "r"(a[mi][0]), "r"(a[mi][1]), "r"(a[mi][2]), "r"(a[mi][3]),
                          "r"(b[ni][0]), "r"(b[ni][1]));
        }
        __syncthreads();
    }

#pragma unroll
    for (int mi = 0; mi < 2; mi++)
#pragma unroll
        for (int ni = 0; ni < 8; ni++) {
            int row0 = m0 + wm + mi * 16 + gq;
            int col = n0 + wn + ni * 8 + 2 * tq;
            *(float2*)&g_X[(size_t)row0 * G4 + col] = make_float2(acc[mi][ni][0], acc[mi][ni][1]);
            *(float2*)&g_X[(size_t)(row0 + 8) * G4 + col] = make_float2(acc[mi][ni][2], acc[mi][ni][3]);
        }
}

// ---- zgemm_tc: K-split x2 + cp.async double-buffered staging. ----
__global__ __launch_bounds__(128) void zgemm_tc(int t) {
    __shared__ __align__(16) __nv_bfloat16 As[2][64][72];
    __shared__ __align__(16) __nv_bfloat16 Bs[2][64][72];
    const int tid = threadIdx.x;
    const int warp = tid >> 5, lane = tid & 31;
    const int gq = lane >> 2, tq = lane & 3;
    const int n0 = blockIdx.x * 64, m0 = blockIdx.y * 64;
    const int sl = blockIdx.z;
    const int kbase = sl * (KB / 2);
    const int wm = (warp & 1) * 32, wn = (warp >> 1) * 32;
    const int arow = tid >> 3, aseg = tid & 7;

    float acc[2][4][4];
    if (sl == 0) {
#pragma unroll
        for (int mi = 0; mi < 2; mi++)
#pragma unroll
            for (int ni = 0; ni < 4; ni++) {
                int row0 = m0 + wm + mi * 16 + gq;
                int col = n0 + wn + ni * 8 + 2 * tq;
                float2 v0 = *(const float2*)&g_X[((size_t)row0 * TT + t) * G4 + col];
                float2 v1 = *(const float2*)&g_X[((size_t)(row0 + 8) * TT + t) * G4 + col];
                acc[mi][ni][0] = v0.x; acc[mi][ni][1] = v0.y;
                acc[mi][ni][2] = v1.x; acc[mi][ni][3] = v1.y;
            }
    } else {
#pragma unroll
        for (int mi = 0; mi < 2; mi++)
#pragma unroll
            for (int ni = 0; ni < 4; ni++)
#pragma unroll
                for (int q = 0; q < 4; q++) acc[mi][ni][q] = 0.f;
    }

    auto stage = [&](int c, int buf) {
        int k0 = kbase + c * KC;
        int ka = (k0 >= 2048) ? (k0 - 2048) : k0;
#pragma unroll
        for (int i = 0; i < 4; i++) {
            cp16(&As[buf][arow + 16 * i][aseg * 8], &g_hA[m0 + arow + 16 * i][ka + aseg * 8]);
            cp16(&Bs[buf][arow + 16 * i][aseg * 8], &g_BT[n0 + arow + 16 * i][k0 + aseg * 8]);
        }
        asm volatile("cp.async.commit_group;");
    };

    stage(0, 0);
    for (int c = 0; c < NCHS; c++) {
        int buf = c & 1;
        if (c + 1 < NCHS) {
            stage(c + 1, buf ^ 1);
            asm volatile("cp.async.wait_group 1;");
        } else {
            asm volatile("cp.async.wait_group 0;");
        }
        __syncthreads();
#pragma unroll
        for (int ks = 0; ks < KC; ks += 16) {
            uint32_t a[2][4], b[4][2];
#pragma unroll
            for (int mi = 0; mi < 2; mi++) {
                a[mi][0] = *(const uint32_t*)&As[buf][wm + mi * 16 + gq    ][ks + 2 * tq];
                a[mi][1] = *(const uint32_t*)&As[buf][wm + mi * 16 + gq + 8][ks + 2 * tq];
                a[mi][2] = *(const uint32_t*)&As[buf][wm + mi * 16 + gq    ][ks + 2 * tq + 8];
                a[mi][3] = *(const uint32_t*)&As[buf][wm + mi * 16 + gq + 8][ks + 2 * tq + 8];
            }
#pragma unroll
            for (int ni = 0; ni < 4; ni++) {
                b[ni][0] = *(const uint32_t*)&Bs[buf][wn + ni * 8 + gq][ks + 2 * tq];
                b[ni][1] = *(const uint32_t*)&Bs[buf][wn + ni * 8 + gq][ks + 2 * tq + 8];
            }
#pragma unroll
            for (int mi = 0; mi < 2; mi++)
#pragma unroll
                for (int ni = 0; ni < 4; ni++)
                    asm volatile(
                        "mma.sync.aligned.m16n8k16.row.col.f32.bf16.bf16.f32 "
                        "{%0,%1,%2,%3}, {%4,%5,%6,%7}, {%8,%9}, {%0,%1,%2,%3};"
                        : "+f"(acc[mi][ni][0]), "+f"(acc[mi][ni][1]),
                          "+f"(acc[mi][ni][2]), "+f"(acc[mi][ni][3])
                        : "r"(a[mi][0]), "r"(a[mi][1]), "r"(a[mi][2]), "r"(a[mi][3]),
                          "r"(b[ni][0]), "r"(b[ni][1]));
        }
        __syncthreads();
    }

#pragma unroll
    for (int mi = 0; mi < 2; mi++)
#pragma unroll
        for (int ni = 0; ni < 4; ni++) {
            int row0 = m0 + wm + mi * 16 + gq;
            int col = n0 + wn + ni * 8 + 2 * tq;
            *(float2*)&g_zp[sl][(size_t)row0 * G4 + col] = make_float2(acc[mi][ni][0], acc[mi][ni][1]);
            *(float2*)&g_zp[sl][(size_t)(row0 + 8) * G4 + col] = make_float2(acc[mi][ni][2], acc[mi][ni][3]);
        }
}

// ---- gate helpers: write c, h (bf16 hi/lo into g_hA), hlast ----
__device__ __forceinline__ void gate_store(int b, int j, const float* zi, const float* zf,
                                           const float* zg, const float* zo,
                                           const float* cp, bool use_cp, bool last) {
    float co[4], ho[4];
#pragma unroll
    for (int l = 0; l < 4; l++) {
        float ig = 1.f / (1.f + expf(-zi[l]));
        float og = 1.f / (1.f + expf(-zo[l]));
        float c = ig * tanhf(zg[l]);
        if (use_cp) {
            float fg = 1.f / (1.f + expf(-zf[l]));
            c += fg * cp[l];
        }
        co[l] = c;
        ho[l] = og * tanhf(c);
    }
    *(float4*)&g_c[b * LH + j] = make_float4(co[0], co[1], co[2], co[3]);
    __nv_bfloat16 hi[4], lo[4];
#pragma unroll
    for (int l = 0; l < 4; l++) {
        hi[l] = __float2bfloat16(ho[l]);
        lo[l] = __float2bfloat16(ho[l] - __bfloat162float(hi[l]));
    }
    __nv_bfloat162* ph = (__nv_bfloat162*)&g_hA[b][j];
    ph[0] = __halves2bfloat162(hi[0], hi[1]);
    ph[1] = __halves2bfloat162(hi[2], hi[3]);
    __nv_bfloat162* pl = (__nv_bfloat162*)&g_hA[b][1024 + j];
    pl[0] = __halves2bfloat162(lo[0], lo[1]);
    pl[1] = __halves2bfloat162(lo[2], lo[3]);
    if (last) *(float4*)&g_hlast[b * LH + j] = make_float4(ho[0], ho[1], ho[2], ho[3]);
}

// ---- t=0: z0 = X[:,0,:], c0 = 0 ----
__global__ void gate0_kernel(const int* __restrict__ length) {
    int b = blockIdx.x;
    int j = threadIdx.x * 4;
    bool last = (length[b] == 1);
    const float* xb = &g_X[(size_t)b * TT * G4];
    float4 zi4 = *(const float4*)&xb[j];
    float4 zg4 = *(const float4*)&xb[j + 2 * LH];
    float4 zo4 = *(const float4*)&xb[j + 3 * LH];
    float zi[4] = {zi4.x, zi4.y, zi4.z, zi4.w};
    float zg[4] = {zg4.x, zg4.y, zg4.z, zg4.w};
    float zo[4] = {zo4.x, zo4.y, zo4.z, zo4.w};
    float dummy[4] = {0, 0, 0, 0};
    gate_store(b, j, zi, dummy, zg, zo, dummy, false, last);
}

// ---- t>=1: gates from g_zp[0]+g_zp[1] ----
__global__ void gate_kernel(const int* __restrict__ length, int t) {
    int b = blockIdx.x;
    int j = threadIdx.x * 4;
    bool last = (length[b] - 1) == t;
    float4 z[4];
#pragma unroll
    for (int g = 0; g < 4; g++) {
        size_t idx = (size_t)b * G4 + g * LH + j;
        float4 s0 = *(const float4*)&g_zp[0][idx];
        float4 s1 = *(const float4*)&g_zp[1][idx];
        z[g].x = s0.x + s1.x; z[g].y = s0.y + s1.y;
        z[g].z = s0.z + s1.z; z[g].w = s0.w + s1.w;
    }
    float4 cp4 = *(const float4*)&g_c[b * LH + j];
    float zi[4] = {z[0].x, z[0].y, z[0].z, z[0].w};
    float zf[4] = {z[1].x, z[1].y, z[1].z, z[1].w};
    float zg[4] = {z[2].x, z[2].y, z[2].z, z[2].w};
    float zo[4] = {z[3].x, z[3].y, z[3].z, z[3].w};
    float cp[4] = {cp4.x, cp4.y, cp4.z, cp4.w};
    gate_store(b, j, zi, zf, zg, zo, cp, true, last);
}

// ---- enc logits = h_last @ W_enc + b_enc ----
__global__ __launch_bounds__(128) void enc_kernel(const float* __restrict__ Wenc,
                                                  const float* __restrict__ benc) {
    const int BT = 8;
    __shared__ __align__(16) float hs[BT * LH];
    int n = blockIdx.x * 128 + threadIdx.x;
    int b0 = blockIdx.y * BT;
    {
        const float4* src = (const float4*)&g_hlast[b0 * LH];
        float4* dst = (float4*)hs;
        for (int i = threadIdx.x; i < BT * LH / 4; i += 128) dst[i] = src[i];
    }
    __syncthreads();
    if (n >= AA) return;
    float acc[BT];
    float bias = benc[n];
#pragma unroll
    for (int bb = 0; bb < BT; bb++) acc[bb] = bias;
    for (int k = 0; k < LH; k += 4) {
        float w0 = Wenc[(size_t)k * AA + n];
        float w1 = Wenc[(size_t)(k + 1) * AA + n];
        float w2 = Wenc[(size_t)(k + 2) * AA + n];
        float w3 = Wenc[(size_t)(k + 3) * AA + n];
#pragma unroll
        for (int bb = 0; bb < BT; bb++) {
            float4 hv = *(const float4*)&hs[bb * LH + k];
            acc[bb] = fmaf(hv.x, w0, acc[bb]);
            acc[bb] = fmaf(hv.y, w1, acc[bb]);
            acc[bb] = fmaf(hv.z, w2, acc[bb]);
            acc[bb] = fmaf(hv.w, w3, acc[bb]);
        }
    }
#pragma unroll
    for (int bb = 0; bb < BT; bb++) g_enc[(b0 + bb) * AA + n] = acc[bb];
}

// ---- final ----
__global__ void final_kernel(float* __restrict__ out) {
    int b = blockIdx.x;
    __shared__ float red[256];
    int tid = threadIdx.x;
    float mx = -3.4e38f;
    for (int a = tid; a < AA; a += blockDim.x) mx = fmaxf(mx, g_enc[b * AA + a]);
    red[tid] = mx; __syncthreads();
    for (int s = 128; s > 0; s >>= 1) { if (tid < s) red[tid] = fmaxf(red[tid], red[tid + s]); __syncthreads(); }
    mx = red[0]; __syncthreads();
    float sum = 0.f;
    for (int a = tid; a < AA; a += blockDim.x) sum += expf(g_enc[b * AA + a] - mx);
    red[tid] = sum; __syncthreads();
    for (int s = 128; s > 0; s >>= 1) { if (tid < s) red[tid] += red[tid + s]; __syncthreads(); }
    float inv = 1.f / red[0];
    for (int a = tid; a < AA; a += blockDim.x) {
        float e = expf(g_enc[b * AA + a] - mx) * inv;
        out[b * AA + a] = sqrtf(g_root[b * AA + a] * e);
    }
}

extern "C" void kernel_launch(void* const* d_in, const int* in_sizes, int n_in,
                              void* d_out, int out_size) {
    const float* features        = (const float*)d_in[0];
    const int* question          = (const int*)d_in[1];
    const int* length            = (const int*)d_in[2];
    const int* yesno             = (const int*)d_in[3];
    const int* root_inst         = (const int*)d_in[4];
    const int* find_inst         = (const int*)d_in[5];
    const float* W_find          = (const float*)d_in[6];
    const float* W_meas1         = (const float*)d_in[7];
    const float* b_meas1         = (const float*)d_in[8];
    const float* W_meas2         = (const float*)d_in[9];
    const float* b_meas2         = (const float*)d_in[10];
    const float* W_desc          = (const float*)d_in[11];
    const float* b_desc          = (const float*)d_in[12];
    const float* E_emb           = (const float*)d_in[13];
    const float* Wx              = (const float*)d_in[14];
    const float* Wh              = (const float*)d_in[15];
    const float* b_lstm          = (const float*)d_in[16];
    const float* W_enc           = (const float*)d_in[17];
    const float* b_enc           = (const float*)d_in[18];
    float* out = (float*)d_out;

    static cudaStream_t s_mod = nullptr;
    static cudaEvent_t ev_fork = nullptr, ev_prep = nullptr, ev_join = nullptr;
    if (s_mod == nullptr) {
        cudaStreamCreateWithFlags(&s_mod, cudaStreamNonBlocking);
        cudaEventCreateWithFlags(&ev_fork, cudaEventDisableTiming);
        cudaEventCreateWithFlags(&ev_prep, cudaEventDisableTiming);
        cudaEventCreateWithFlags(&ev_join, cudaEventDisableTiming);
    }

    // fork: Wh prep + module network on side stream
    cudaEventRecord(ev_fork, 0);
    cudaStreamWaitEvent(s_mod, ev_fork, 0);
    prep_kernel<<<dim3(G4 / 32, LH / 32), 256, 0, s_mod>>>(Wh);
    cudaEventRecord(ev_prep, s_mod);
    find_kernel<<<BN, 256, 0, s_mod>>>(features, find_inst, W_find);
    attend_kernel<<<BN, 512, 0, s_mod>>>(features);
    measure_kernel<<<dim3(2, BN), 256, 0, s_mod>>>(root_inst, yesno, W_meas1, b_meas1);
    rootlogits_kernel<<<dim3(8, BN), 256, 0, s_mod>>>(root_inst, yesno, W_meas2, b_meas2, W_desc, b_desc);
    softmax_root_kernel<<<BN, 256, 0, s_mod>>>();
    cudaEventRecord(ev_join, s_mod);

    // main: question encoder (xw on tensor cores)
    prep_xA<<<MROWS, XKP>>>(question, E_emb);
    prep_xB<<<dim3(G4 / 32, XKP / 32), 256>>>(Wx);
    xw_tc<<<dim3(G4 / 128, MROWS / 128), 256>>>(b_lstm);
    gate0_kernel<<<BN, 256>>>(length);
    cudaStreamWaitEvent(0, ev_prep, 0);
    for (int t = 1; t < TT; t++) {
        zgemm_tc<<<dim3(G4 / 64, BN / 64, 2), 128>>>(t);
        gate_kernel<<<BN, 256>>>(length, t);
    }
    enc_kernel<<<dim3((AA + 127) / 128, BN / 8), 128>>>(W_enc, b_enc);

    // join
    cudaStreamWaitEvent(0, ev_join, 0);
    final_kernel<<<BN, 256>>>(out);
}

// round 17
// speedup vs baseline: 1.4791x; 1.0134x over previous
#include <cuda_runtime.h>
#include <cuda_bf16.h>
#include <stdint.h>
#include <math.h>

// ---- problem dims ----
#define BN 128
#define CC 512
#define HW 196
#define KF 2
#define AA 2000
#define TT 20
#define EE 300
#define LH 1024
#define MH 512
#define G4 4096   // 4*LH
#define KB 3072   // LSTM split-bf16 GEMM K (= 3*LH)
#define KC 64     // LSTM K chunk
#define NCHS 24   // chunks per K slice (KB/2/KC)
#define XKP 320   // padded emb K segment (300 -> 320)
#define XKB 960   // xw split K total (3*320)
#define XKC 32    // xw K chunk
#define XNCH (XKB / XKC)  // 30
#define MROWS (BN * TT)   // 2560

// ---- scratch (device globals; no runtime allocation) ----
__device__ float g_maps[BN * HW];
__device__ float g_denom[BN];
__device__ float g_hmeas[BN * MH];
__device__ float g_att[BN * CC];
__device__ float g_root[BN * AA];
__device__ float g_X[(size_t)BN * TT * G4];     // emb@Wx + b_lstm
__device__ float g_zp[2][BN * G4];              // per-K-slice gate partials
__device__ __nv_bfloat16 g_hA[BN][2048];        // [m][k]: Hh | Hl
__device__ __nv_bfloat16 g_BT[G4][KB];          // [n][k]: Wh_h | Wh_h | Wh_l
__device__ __nv_bfloat16 g_XA[MROWS][2 * XKP];  // [row][k]: Ehi(0..319) | Elo(320..639)
__device__ __nv_bfloat16 g_XBT[G4][XKB];        // [n][k]: Wx_h | Wx_h | Wx_l
__device__ float g_c[BN * LH];
__device__ float g_hlast[BN * LH];
__device__ float g_enc[BN * AA];

__device__ __forceinline__ void cp16(void* smem, const void* gmem) {
    uint32_t s = (uint32_t)__cvta_generic_to_shared(smem);
    asm volatile("cp.async.ca.shared.global [%0], [%1], 16;" :: "r"(s), "l"(gmem));
}

// ---- prep: transpose + split Wh into g_BT (bf16 hi/hi/lo) ----
__global__ void prep_kernel(const float* __restrict__ Wh) {
    __shared__ float tile[32][33];
    int kt = blockIdx.y * 32;
    int nt = blockIdx.x * 32;
    int tx = threadIdx.x & 31, ty = threadIdx.x >> 5;
    for (int r = ty; r < 32; r += 8)
        tile[r][tx] = Wh[(size_t)(kt + r) * G4 + nt + tx];
    __syncthreads();
    for (int r = ty; r < 32; r += 8) {
        int n = nt + r;
        float v = tile[tx][r];
        __nv_bfloat16 hi = __float2bfloat16(v);
        __nv_bfloat16 lo = __float2bfloat16(v - __bfloat162float(hi));
        g_BT[n][kt + tx]        = hi;
        g_BT[n][1024 + kt + tx] = hi;
        g_BT[n][2048 + kt + tx] = lo;
    }
}

// ---- prep xA: gather embeddings, split hi/lo, pad to 320 ----
__global__ void prep_xA(const int* __restrict__ question,
                        const float* __restrict__ Eemb) {
    int r = blockIdx.x;           // 0..2559
    int j = threadIdx.x;          // 0..319
    int tok = question[r];
    __nv_bfloat16 hi = __float2bfloat16(0.f), lo = hi;
    if (j < EE) {
        float v = Eemb[(size_t)tok * EE + j];
        hi = __float2bfloat16(v);
        lo = __float2bfloat16(v - __bfloat162float(hi));
    }
    g_XA[r][j] = hi;
    g_XA[r][XKP + j] = lo;
}

// ---- prep xB: transpose + split Wx into g_XBT (hi/hi/lo, padded) ----
__global__ void prep_xB(const float* __restrict__ Wx) {
    __shared__ float tile[32][33];
    int kt = blockIdx.y * 32;     // 0..288 (10 tiles, covers 320)
    int nt = blockIdx.x * 32;
    int tx = threadIdx.x & 31, ty = threadIdx.x >> 5;
    for (int r = ty; r < 32; r += 8) {
        int k = kt + r;
        tile[r][tx] = (k < EE) ? Wx[(size_t)k * G4 + nt + tx] : 0.f;
    }
    __syncthreads();
    for (int r = ty; r < 32; r += 8) {
        int n = nt + r;
        float v = tile[tx][r];
        __nv_bfloat16 hi = __float2bfloat16(v);
        __nv_bfloat16 lo = __float2bfloat16(v - __bfloat162float(hi));
        g_XBT[n][kt + tx]            = hi;
        g_XBT[n][XKP + kt + tx]      = hi;
        g_XBT[n][2 * XKP + kt + tx]  = lo;
    }
}

// ---- Find ----
__global__ void find_kernel(const float* __restrict__ feat,
                            const int* __restrict__ find_inst,
                            const float* __restrict__ W_find) {
    int b = blockIdx.x;
    __shared__ float w0[CC], w1[CC];
    __shared__ float red[256];
    int i0 = find_inst[b * KF + 0], i1 = find_inst[b * KF + 1];
    for (int c = threadIdx.x; c < CC; c += blockDim.x) {
        w0[c] = W_find[(size_t)i0 * CC + c];
        w1[c] = W_find[(size_t)i1 * CC + c];
    }
    __syncthreads();
    float m = 0.f;
    int t = threadIdx.x;
    if (t < HW) {
        const float* fb = feat + (size_t)b * CC * HW + t;
        float a0 = 0.f, a1 = 0.f;
#pragma unroll 4
        for (int c = 0; c < CC; c++) {
            float f = fb[(size_t)c * HW];
            a0 = fmaf(w0[c], f, a0);
            a1 = fmaf(w1[c], f, a1);
        }
        a0 = fmaxf(a0, 0.f); a1 = fmaxf(a1, 0.f);
        m = a0 * a1;
        g_maps[b * HW + t] = m;
    }
    red[threadIdx.x] = m; __syncthreads();
    for (int s = 128; s > 0; s >>= 1) {
        if (threadIdx.x < s) red[threadIdx.x] += red[threadIdx.x + s];
        __syncthreads();
    }
    if (threadIdx.x == 0) g_denom[b] = red[0] + 1e-6f;
}

// ---- Describe attend ----
__global__ void attend_kernel(const float* __restrict__ feat) {
    int b = blockIdx.x;
    __shared__ float ms[HW];
    float inv = 1.f / g_denom[b];
    for (int t = threadIdx.x; t < HW; t += blockDim.x) ms[t] = g_maps[b * HW + t] * inv;
    __syncthreads();
    int c = threadIdx.x;
    const float4* fb = (const float4*)(feat + (size_t)(b * CC + c) * HW);
    float acc = 0.f;
    for (int q = 0; q < HW / 4; q++) {
        float4 f = fb[q];
        acc = fmaf(ms[4 * q + 0], f.x, acc);
        acc = fmaf(ms[4 * q + 1], f.y, acc);
        acc = fmaf(ms[4 * q + 2], f.z, acc);
        acc = fmaf(ms[4 * q + 3], f.w, acc);
    }
    g_att[b * CC + c] = acc;
}

// ---- Measure hidden ----
__global__ void measure_kernel(const int* __restrict__ root,
                               const int* __restrict__ yes,
                               const float* __restrict__ W1,
                               const float* __restrict__ b1) {
    int b = blockIdx.y;
    if (yes[b] == 0) return;
    __shared__ float mf[HW];
    for (int t = threadIdx.x; t < HW; t += blockDim.x) mf[t] = g_maps[b * HW + t];
    __syncthreads();
    int m = blockIdx.x * 256 + threadIdx.x;
    int r = root[b];
    const float* W = W1 + (size_t)r * HW * MH + m;
    float acc = b1[r * MH + m];
#pragma unroll 4
    for (int i = 0; i < HW; i++) acc = fmaf(mf[i], W[(size_t)i * MH], acc);
    g_hmeas[b * MH + m] = fmaxf(acc, 0.f);
}

// ---- Root logits ----
__global__ void rootlogits_kernel(const int* __restrict__ root,
                                  const int* __restrict__ yes,
                                  const float* __restrict__ Wm2,
                                  const float* __restrict__ bm2,
                                  const float* __restrict__ Wd,
                                  const float* __restrict__ bd) {
    int b = blockIdx.y;
    int a = blockIdx.x * blockDim.x + threadIdx.x;
    __shared__ float v[512];
    bool y = yes[b] != 0;
    int r = root[b];
    const float* src = y ? &g_hmeas[b * MH] : &g_att[b * CC];
    for (int i = threadIdx.x; i < 512; i += blockDim.x) v[i] = src[i];
    __syncthreads();
    if (a >= AA) return;
    const float* W = y ? (Wm2 + a) : (Wd + (size_t)r * CC * AA + a);
    float acc = y ? bm2[a] : bd[r * AA + a];
#pragma unroll 4
    for (int i = 0; i < 512; i++) acc = fmaf(v[i], W[(size_t)i * AA], acc);
    g_root[b * AA + a] = acc;
}

// ---- softmax over root logits ----
__global__ void softmax_root_kernel() {
    int b = blockIdx.x;
    __shared__ float red[256];
    int tid = threadIdx.x;
    float mx = -3.4e38f;
    for (int a = tid; a < AA; a += blockDim.x) mx = fmaxf(mx, g_root[b * AA + a]);
    red[tid] = mx; __syncthreads();
    for (int s = 128; s > 0; s >>= 1) { if (tid < s) red[tid] = fmaxf(red[tid], red[tid + s]); __syncthreads(); }
    mx = red[0]; __syncthreads();
    float sum = 0.f;
    for (int a = tid; a < AA; a += blockDim.x) {
        float e = expf(g_root[b * AA + a] - mx);
        g_root[b * AA + a] = e;
        sum += e;
    }
    red[tid] = sum; __syncthreads();
    for (int s = 128; s > 0; s >>= 1) { if (tid < s) red[tid] += red[tid + s]; __syncthreads(); }
    float inv = 1.f / red[0];
    for (int a = tid; a < AA; a += blockDim.x) g_root[b * AA + a] *= inv;
}

// ---- xw_tc: X = [Ehi|Elo|Ehi] @ g_XBT^T + b_lstm via mma.sync bf16.
//      grid (32, 20), 256 thr (8 warps, 4m x 2n), tile 128x128, XKC=32. ----
__global__ __launch_bounds__(256) void xw_tc(const float* __restrict__ b_lstm) {
    __shared__ __align__(16) __nv_bfloat16 As[2][128][40];  // 20 KB
    __shared__ __align__(16) __nv_bfloat16 Bs[2][128][40];  // 20 KB
    const int tid = threadIdx.x;
    const int warp = tid >> 5, lane = tid & 31;
    const int gq = lane >> 2, tq = lane & 3;
    const int n0 = blockIdx.x * 128, m0 = blockIdx.y * 128;
    const int wm = (warp & 3) * 32, wn = (warp >> 2) * 64;
    const int arow = tid >> 2, aseg = tid & 3;   // rows 0..63 (+64), 4x16B segs

    float acc[2][8][4];
#pragma unroll
    for (int ni = 0; ni < 8; ni++) {
        int col = n0 + wn + ni * 8 + 2 * tq;
        float2 bv = *(const float2*)&b_lstm[col];
#pragma unroll
        for (int mi = 0; mi < 2; mi++) {
            acc[mi][ni][0] = bv.x; acc[mi][ni][1] = bv.y;
            acc[mi][ni][2] = bv.x; acc[mi][ni][3] = bv.y;
        }
    }

    auto stage = [&](int c, int buf) {
        int k0 = c * XKC;
        int ka = (k0 >= 2 * XKP) ? k0 - 2 * XKP : k0;  // A: [hi|lo|hi]
#pragma unroll
        for (int half = 0; half < 2; half++) {
            int r = arow + half * 64;
            cp16(&As[buf][r][aseg * 8], &g_XA[m0 + r][ka + aseg * 8]);
            cp16(&Bs[buf][r][aseg * 8], &g_XBT[n0 + r][k0 + aseg * 8]);
        }
        asm volatile("cp.async.commit_group;");
    };

    stage(0, 0);
    for (int c = 0; c < XNCH; c++) {
        int buf = c & 1;
        if (c + 1 < XNCH) {
            stage(c + 1, buf ^ 1);
            asm volatile("cp.async.wait_group 1;");
        } else {
            asm volatile("cp.async.wait_group 0;");
        }
        __syncthreads();
#pragma unroll
        for (int ks = 0; ks < XKC; ks += 16) {
            uint32_t a[2][4], b[8][2];
#pragma unroll
            for (int mi = 0; mi < 2; mi++) {
                a[mi][0] = *(const uint32_t*)&As[buf][wm + mi * 16 + gq    ][ks + 2 * tq];
                a[mi][1] = *(const uint32_t*)&As[buf][wm + mi * 16 + gq + 8][ks + 2 * tq];
                a[mi][2] = *(const uint32_t*)&As[buf][wm + mi * 16 + gq    ][ks + 2 * tq + 8];
                a[mi][3] = *(const uint32_t*)&As[buf][wm + mi * 16 + gq + 8][ks + 2 * tq + 8];
            }
#pragma unroll
            for (int ni = 0; ni < 8; ni++) {
                b[ni][0] = *(const uint32_t*)&Bs[buf][wn + ni * 8 + gq][ks + 2 * tq];
                b[ni][1] = *(const uint32_t*)&Bs[buf][wn + ni * 8 + gq][ks + 2 * tq + 8];
            }
#pragma unroll
            for (int mi = 0; mi < 2; mi++)
#pragma unroll
                for (int ni = 0; ni < 8; ni++)
                    asm volatile(
                        "mma.sync.aligned.m16n8k16.row.col.f32.bf16.bf16.f32 "
                        "{%0,%1,%2,%3}, {%4,%5,%6,%7}, {%8,%9}, {%0,%1,%2,%3};"
                        : "+f"(acc[mi][ni][0]), "+f"(acc[mi][ni][1]),
                          "+f"(acc[mi][ni][2]), "+f"(acc[mi][ni][3])
                        : "r"(a[mi][0]), "r"(a[mi][1]), "r"(a[mi][2]), "r"(a[mi][3]),
                          "r"(b[ni][0]), "r"(b[ni][1]));
        }
        __syncthreads();
    }

#pragma unroll
    for (int mi = 0; mi < 2; mi++)
#pragma unroll
        for (int ni = 0; ni < 8; ni++) {
            int row0 = m0 + wm + mi * 16 + gq;
            int col = n0 + wn + ni * 8 + 2 * tq;
            *(float2*)&g_X[(size_t)row0 * G4 + col] = make_float2(acc[mi][ni][0], acc[mi][ni][1]);
            *(float2*)&g_X[(size_t)(row0 + 8) * G4 + col] = make_float2(acc[mi][ni][2], acc[mi][ni][3]);
        }
}

// ---- zgemm_tc: K-split x2 + cp.async double-buffered staging. ----
__global__ __launch_bounds__(128) void zgemm_tc(int t) {
    __shared__ __align__(16) __nv_bfloat16 As[2][64][72];
    __shared__ __align__(16) __nv_bfloat16 Bs[2][64][72];
    const int tid = threadIdx.x;
    const int warp = tid >> 5, lane = tid & 31;
    const int gq = lane >> 2, tq = lane & 3;
    const int n0 = blockIdx.x * 64, m0 = blockIdx.y * 64;
    const int sl = blockIdx.z;
    const int kbase = sl * (KB / 2);
    const int wm = (warp & 1) * 32, wn = (warp >> 1) * 32;
    const int arow = tid >> 3, aseg = tid & 7;

    float acc[2][4][4];
    if (sl == 0) {
#pragma unroll
        for (int mi = 0; mi < 2; mi++)
#pragma unroll
            for (int ni = 0; ni < 4; ni++) {
                int row0 = m0 + wm + mi * 16 + gq;
                int col = n0 + wn + ni * 8 + 2 * tq;
                float2 v0 = *(const float2*)&g_X[((size_t)row0 * TT + t) * G4 + col];
                float2 v1 = *(const float2*)&g_X[((size_t)(row0 + 8) * TT + t) * G4 + col];
                acc[mi][ni][0] = v0.x; acc[mi][ni][1] = v0.y;
                acc[mi][ni][2] = v1.x; acc[mi][ni][3] = v1.y;
            }
    } else {
#pragma unroll
        for (int mi = 0; mi < 2; mi++)
#pragma unroll
            for (int ni = 0; ni < 4; ni++)
#pragma unroll
                for (int q = 0; q < 4; q++) acc[mi][ni][q] = 0.f;
    }

    auto stage = [&](int c, int buf) {
        int k0 = kbase + c * KC;
        int ka = (k0 >= 2048) ? (k0 - 2048) : k0;
#pragma unroll
        for (int i = 0; i < 4; i++) {
            cp16(&As[buf][arow + 16 * i][aseg * 8], &g_hA[m0 + arow + 16 * i][ka + aseg * 8]);
            cp16(&Bs[buf][arow + 16 * i][aseg * 8], &g_BT[n0 + arow + 16 * i][k0 + aseg * 8]);
        }
        asm volatile("cp.async.commit_group;");
    };

    stage(0, 0);
    for (int c = 0; c < NCHS; c++) {
        int buf = c & 1;
        if (c + 1 < NCHS) {
            stage(c + 1, buf ^ 1);
            asm volatile("cp.async.wait_group 1;");
        } else {
            asm volatile("cp.async.wait_group 0;");
        }
        __syncthreads();
#pragma unroll
        for (int ks = 0; ks < KC; ks += 16) {
            uint32_t a[2][4], b[4][2];
#pragma unroll
            for (int mi = 0; mi < 2; mi++) {
                a[mi][0] = *(const uint32_t*)&As[buf][wm + mi * 16 + gq    ][ks + 2 * tq];
                a[mi][1] = *(const uint32_t*)&As[buf][wm + mi * 16 + gq + 8][ks + 2 * tq];
                a[mi][2] = *(const uint32_t*)&As[buf][wm + mi * 16 + gq    ][ks + 2 * tq + 8];
                a[mi][3] = *(const uint32_t*)&As[buf][wm + mi * 16 + gq + 8][ks + 2 * tq + 8];
            }
#pragma unroll
            for (int ni = 0; ni < 4; ni++) {
                b[ni][0] = *(const uint32_t*)&Bs[buf][wn + ni * 8 + gq][ks + 2 * tq];
                b[ni][1] = *(const uint32_t*)&Bs[buf][wn + ni * 8 + gq][ks + 2 * tq + 8];
            }
#pragma unroll
            for (int mi = 0; mi < 2; mi++)
#pragma unroll
                for (int ni = 0; ni < 4; ni++)
                    asm volatile(
                        "mma.sync.aligned.m16n8k16.row.col.f32.bf16.bf16.f32 "
                        "{%0,%1,%2,%3}, {%4,%5,%6,%7}, {%8,%9}, {%0,%1,%2,%3};"
                        : "+f"(acc[mi][ni][0]), "+f"(acc[mi][ni][1]),
                          "+f"(acc[mi][ni][2]), "+f"(acc[mi][ni][3])
                        : "r"(a[mi][0]), "r"(a[mi][1]), "r"(a[mi][2]), "r"(a[mi][3]),
                          "r"(b[ni][0]), "r"(b[ni][1]));
        }
        __syncthreads();
    }

#pragma unroll
    for (int mi = 0; mi < 2; mi++)
#pragma unroll
        for (int ni = 0; ni < 4; ni++) {
            int row0 = m0 + wm + mi * 16 + gq;
            int col = n0 + wn + ni * 8 + 2 * tq;
            *(float2*)&g_zp[sl][(size_t)row0 * G4 + col] = make_float2(acc[mi][ni][0], acc[mi][ni][1]);
            *(float2*)&g_zp[sl][(size_t)(row0 + 8) * G4 + col] = make_float2(acc[mi][ni][2], acc[mi][ni][3]);
        }
}

// ---- gate helpers: write c, h (bf16 hi/lo into g_hA), hlast ----
__device__ __forceinline__ void gate_store(int b, int j, const float* zi, const float* zf,
                                           const float* zg, const float* zo,
                                           const float* cp, bool use_cp, bool last) {
    float co[4], ho[4];
#pragma unroll
    for (int l = 0; l < 4; l++) {
        float ig = 1.f / (1.f + expf(-zi[l]));
        float og = 1.f / (1.f + expf(-zo[l]));
        float c = ig * tanhf(zg[l]);
        if (use_cp) {
            float fg = 1.f / (1.f + expf(-zf[l]));
            c += fg * cp[l];
        }
        co[l] = c;
        ho[l] = og * tanhf(c);
    }
    *(float4*)&g_c[b * LH + j] = make_float4(co[0], co[1], co[2], co[3]);
    __nv_bfloat16 hi[4], lo[4];
#pragma unroll
    for (int l = 0; l < 4; l++) {
        hi[l] = __float2bfloat16(ho[l]);
        lo[l] = __float2bfloat16(ho[l] - __bfloat162float(hi[l]));
    }
    __nv_bfloat162* ph = (__nv_bfloat162*)&g_hA[b][j];
    ph[0] = __halves2bfloat162(hi[0], hi[1]);
    ph[1] = __halves2bfloat162(hi[2], hi[3]);
    __nv_bfloat162* pl = (__nv_bfloat162*)&g_hA[b][1024 + j];
    pl[0] = __halves2bfloat162(lo[0], lo[1]);
    pl[1] = __halves2bfloat162(lo[2], lo[3]);
    if (last) *(float4*)&g_hlast[b * LH + j] = make_float4(ho[0], ho[1], ho[2], ho[3]);
}

// ---- t=0: z0 = X[:,0,:], c0 = 0 ----
__global__ void gate0_kernel(const int* __restrict__ length) {
    int b = blockIdx.x;
    int j = threadIdx.x * 4;
    bool last = (length[b] == 1);
    const float* xb = &g_X[(size_t)b * TT * G4];
    float4 zi4 = *(const float4*)&xb[j];
    float4 zg4 = *(const float4*)&xb[j + 2 * LH];
    float4 zo4 = *(const float4*)&xb[j + 3 * LH];
    float zi[4] = {zi4.x, zi4.y, zi4.z, zi4.w};
    float zg[4] = {zg4.x, zg4.y, zg4.z, zg4.w};
    float zo[4] = {zo4.x, zo4.y, zo4.z, zo4.w};
    float dummy[4] = {0, 0, 0, 0};
    gate_store(b, j, zi, dummy, zg, zo, dummy, false, last);
}

// ---- t>=1: gates from g_zp[0]+g_zp[1] ----
__global__ void gate_kernel(const int* __restrict__ length, int t) {
    int b = blockIdx.x;
    int j = threadIdx.x * 4;
    bool last = (length[b] - 1) == t;
    float4 z[4];
#pragma unroll
    for (int g = 0; g < 4; g++) {
        size_t idx = (size_t)b * G4 + g * LH + j;
        float4 s0 = *(const float4*)&g_zp[0][idx];
        float4 s1 = *(const float4*)&g_zp[1][idx];
        z[g].x = s0.x + s1.x; z[g].y = s0.y + s1.y;
        z[g].z = s0.z + s1.z; z[g].w = s0.w + s1.w;
    }
    float4 cp4 = *(const float4*)&g_c[b * LH + j];
    float zi[4] = {z[0].x, z[0].y, z[0].z, z[0].w};
    float zf[4] = {z[1].x, z[1].y, z[1].z, z[1].w};
    float zg[4] = {z[2].x, z[2].y, z[2].z, z[2].w};
    float zo[4] = {z[3].x, z[3].y, z[3].z, z[3].w};
    float cp[4] = {cp4.x, cp4.y, cp4.z, cp4.w};
    gate_store(b, j, zi, zf, zg, zo, cp, true, last);
}

// ---- enc logits = h_last @ W_enc + b_enc ----
__global__ __launch_bounds__(128) void enc_kernel(const float* __restrict__ Wenc,
                                                  const float* __restrict__ benc) {
    const int BT = 8;
    __shared__ __align__(16) float hs[BT * LH];
    int n = blockIdx.x * 128 + threadIdx.x;
    int b0 = blockIdx.y * BT;
    {
        const float4* src = (const float4*)&g_hlast[b0 * LH];
        float4* dst = (float4*)hs;
        for (int i = threadIdx.x; i < BT * LH / 4; i += 128) dst[i] = src[i];
    }
    __syncthreads();
    if (n >= AA) return;
    float acc[BT];
    float bias = benc[n];
#pragma unroll
    for (int bb = 0; bb < BT; bb++) acc[bb] = bias;
    for (int k = 0; k < LH; k += 4) {
        float w0 = Wenc[(size_t)k * AA + n];
        float w1 = Wenc[(size_t)(k + 1) * AA + n];
        float w2 = Wenc[(size_t)(k + 2) * AA + n];
        float w3 = Wenc[(size_t)(k + 3) * AA + n];
#pragma unroll
        for (int bb = 0; bb < BT; bb++) {
            float4 hv = *(const float4*)&hs[bb * LH + k];
            acc[bb] = fmaf(hv.x, w0, acc[bb]);
            acc[bb] = fmaf(hv.y, w1, acc[bb]);
            acc[bb] = fmaf(hv.z, w2, acc[bb]);
            acc[bb] = fmaf(hv.w, w3, acc[bb]);
        }
    }
#pragma unroll
    for (int bb = 0; bb < BT; bb++) g_enc[(b0 + bb) * AA + n] = acc[bb];
}

// ---- final ----
__global__ void final_kernel(float* __restrict__ out) {
    int b = blockIdx.x;
    __shared__ float red[256];
    int tid = threadIdx.x;
    float mx = -3.4e38f;
    for (int a = tid; a < AA; a += blockDim.x) mx = fmaxf(mx, g_enc[b * AA + a]);
    red[tid] = mx; __syncthreads();
    for (int s = 128; s > 0; s >>= 1) { if (tid < s) red[tid] = fmaxf(red[tid], red[tid + s]); __syncthreads(); }
    mx = red[0]; __syncthreads();
    float sum = 0.f;
    for (int a = tid; a < AA; a += blockDim.x) sum += expf(g_enc[b * AA + a] - mx);
    red[tid] = sum; __syncthreads();
    for (int s = 128; s > 0; s >>= 1) { if (tid < s) red[tid] += red[tid + s]; __syncthreads(); }
    float inv = 1.f / red[0];
    for (int a = tid; a < AA; a += blockDim.x) {
        float e = expf(g_enc[b * AA + a] - mx) * inv;
        out[b * AA + a] = sqrtf(g_root[b * AA + a] * e);
    }
}

extern "C" void kernel_launch(void* const* d_in, const int* in_sizes, int n_in,
                              void* d_out, int out_size) {
    const float* features        = (const float*)d_in[0];
    const int* question          = (const int*)d_in[1];
    const int* length            = (const int*)d_in[2];
    const int* yesno             = (const int*)d_in[3];
    const int* root_inst         = (const int*)d_in[4];
    const int* find_inst         = (const int*)d_in[5];
    const float* W_find          = (const float*)d_in[6];
    const float* W_meas1         = (const float*)d_in[7];
    const float* b_meas1         = (const float*)d_in[8];
    const float* W_meas2         = (const float*)d_in[9];
    const float* b_meas2         = (const float*)d_in[10];
    const float* W_desc          = (const float*)d_in[11];
    const float* b_desc          = (const float*)d_in[12];
    const float* E_emb           = (const float*)d_in[13];
    const float* Wx              = (const float*)d_in[14];
    const float* Wh              = (const float*)d_in[15];
    const float* b_lstm          = (const float*)d_in[16];
    const float* W_enc           = (const float*)d_in[17];
    const float* b_enc           = (const float*)d_in[18];
    float* out = (float*)d_out;

    static cudaStream_t s_mod = nullptr;
    static cudaEvent_t ev_fork = nullptr, ev_prep = nullptr, ev_join = nullptr;
    if (s_mod == nullptr) {
        cudaStreamCreateWithFlags(&s_mod, cudaStreamNonBlocking);
        cudaEventCreateWithFlags(&ev_fork, cudaEventDisableTiming);
        cudaEventCreateWithFlags(&ev_prep, cudaEventDisableTiming);
        cudaEventCreateWithFlags(&ev_join, cudaEventDisableTiming);
    }

    // fork: Wh prep + module network on side stream
    cudaEventRecord(ev_fork, 0);
    cudaStreamWaitEvent(s_mod, ev_fork, 0);
    prep_kernel<<<dim3(G4 / 32, LH / 32), 256, 0, s_mod>>>(Wh);
    cudaEventRecord(ev_prep, s_mod);
    find_kernel<<<BN, 256, 0, s_mod>>>(features, find_inst, W_find);
    attend_kernel<<<BN, 512, 0, s_mod>>>(features);
    measure_kernel<<<dim3(2, BN), 256, 0, s_mod>>>(root_inst, yesno, W_meas1, b_meas1);
    rootlogits_kernel<<<dim3(8, BN), 256, 0, s_mod>>>(root_inst, yesno, W_meas2, b_meas2, W_desc, b_desc);
    softmax_root_kernel<<<BN, 256, 0, s_mod>>>();
    cudaEventRecord(ev_join, s_mod);

    // main: question encoder (xw on tensor cores)
    prep_xA<<<MROWS, XKP>>>(question, E_emb);
    prep_xB<<<dim3(G4 / 32, XKP / 32), 256>>>(Wx);
    xw_tc<<<dim3(G4 / 128, MROWS / 128), 256>>>(b_lstm);
    gate0_kernel<<<BN, 256>>>(length);
    cudaStreamWaitEvent(0, ev_prep, 0);
    for (int t = 1; t < TT; t++) {
        zgemm_tc<<<dim3(G4 / 64, BN / 64, 2), 128>>>(t);
        gate_kernel<<<BN, 256>>>(length, t);
    }
    enc_kernel<<<dim3((AA + 127) / 128, BN / 8), 128>>>(W_enc, b_enc);

    // join
    cudaStreamWaitEvent(0, ev_join, 0);
    final_kernel<<<BN, 256>>>(out);
}